// round 13
// baseline (speedup 1.0000x reference)
#include <cuda_runtime.h>
#include <cuda_bf16.h>
#include <cstdint>
#include <math.h>

#define BATCH 1280
#define EDIM  512
#define D2    1024
#define D6    3072
#define TV    64
#define BN_EPS 1e-5f

#define ROWB 80              // padded smem row stride bytes (40 bf16)

// ---------------- device globals (scratch; zero-initialized) ----------------
__device__ __align__(16) float g_h [BATCH * EDIM];
__device__ __align__(16) __nv_bfloat16 g_qm_hi[BATCH * D2], g_qm_lo[BATCH * D2];
__device__ __align__(16) __nv_bfloat16 g_am_hi[BATCH * D2], g_am_lo[BATCH * D2];
__device__ __align__(16) __nv_bfloat16 g_X_hi[BATCH * D6],  g_X_lo[BATCH * D6];
__device__ __align__(16) __nv_bfloat16 g_WqT_hi[EDIM * D2],  g_WqT_lo[EDIM * D2];
__device__ __align__(16) __nv_bfloat16 g_WaT_hi[EDIM * D2],  g_WaT_lo[EDIM * D2];
__device__ __align__(16) __nv_bfloat16 g_Wc1T_hi[EDIM * D6], g_Wc1T_lo[EDIM * D6];
__device__ float g_sum[EDIM], g_sumsq[EDIM];

__device__ __forceinline__ void split_store(__nv_bfloat16* hi, __nv_bfloat16* lo,
                                            size_t idx, float v) {
    __nv_bfloat16 h = __float2bfloat16(v);
    hi[idx] = h;
    lo[idx] = __float2bfloat16(v - __bfloat162float(h));
}

__device__ __forceinline__ uint32_t pack_bf16x2(float a, float b) {
    __nv_bfloat16 ha = __float2bfloat16(a), hb = __float2bfloat16(b);
    uint16_t ua, ub;
    memcpy(&ua, &ha, 2); memcpy(&ub, &hb, 2);
    return (uint32_t)ua | ((uint32_t)ub << 16);
}

__device__ __forceinline__ uint32_t smem_u32(const void* p) {
    uint32_t a;
    asm("{ .reg .u64 t; cvta.to.shared.u64 t, %1; cvt.u32.u64 %0, t; }"
        : "=r"(a) : "l"(p));
    return a;
}

__device__ __forceinline__ void ldmat4(uint32_t* r, uint32_t addr) {
    asm volatile("ldmatrix.sync.aligned.m8n8.x4.shared.b16 {%0,%1,%2,%3}, [%4];"
                 : "=r"(r[0]), "=r"(r[1]), "=r"(r[2]), "=r"(r[3]) : "r"(addr));
}

__device__ __forceinline__ void mma_bf16(float* c, const uint32_t* a,
                                         uint32_t b0, uint32_t b1) {
    asm volatile(
        "mma.sync.aligned.m16n8k16.row.col.f32.bf16.bf16.f32 "
        "{%0,%1,%2,%3}, {%4,%5,%6,%7}, {%8,%9}, {%0,%1,%2,%3};"
        : "+f"(c[0]), "+f"(c[1]), "+f"(c[2]), "+f"(c[3])
        : "r"(a[0]), "r"(a[1]), "r"(a[2]), "r"(a[3]), "r"(b0), "r"(b1));
}

#define CP16(dst, src) \
    asm volatile("cp.async.cg.shared.global [%0], [%1], 16;" \
                 :: "r"(dst), "l"(src) : "memory")
#define CP_COMMIT() asm volatile("cp.async.commit_group;" ::: "memory")
#define CP_WAIT1()  asm volatile("cp.async.wait_group 1;" ::: "memory")

// ---------------- small weight transpose+split (Wq/Wa via z) + stats zero ---
__global__ void wsplit_small_kernel(const float* __restrict__ Wq,
                                    const float* __restrict__ Wa) {
    const int which = blockIdx.z;
    const float* W = which ? Wa : Wq;
    __nv_bfloat16* oh = which ? g_WaT_hi : g_WqT_hi;
    __nv_bfloat16* ol = which ? g_WaT_lo : g_WqT_lo;
    const int tid = threadIdx.y * 32 + threadIdx.x;
    if (which == 0 && blockIdx.x == 0 && blockIdx.y == 0) {
        g_sum[tid] = 0.f; g_sum[tid + 256] = 0.f;
        g_sumsq[tid] = 0.f; g_sumsq[tid + 256] = 0.f;
    }
    __shared__ float t[64][33];
    const int k0 = blockIdx.x * 64, n0 = blockIdx.y * 32;
    const int tx = threadIdx.x, ty = threadIdx.y;
    #pragma unroll
    for (int i = ty; i < 64; i += 8)
        t[i][tx] = W[(size_t)(k0 + i) * EDIM + n0 + tx];
    __syncthreads();
    #pragma unroll
    for (int i = ty; i < 32; i += 8) {
        const float v0 = t[2 * tx][i], v1 = t[2 * tx + 1][i];
        const __nv_bfloat16 h0 = __float2bfloat16(v0);
        const __nv_bfloat16 h1 = __float2bfloat16(v1);
        const size_t o = (size_t)(n0 + i) * D2 + k0 + 2 * tx;
        *(uint32_t*)&oh[o] = pack_bf16x2(v0, v1);
        *(uint32_t*)&ol[o] = pack_bf16x2(v0 - __bfloat162float(h0),
                                         v1 - __bfloat162float(h1));
    }
}

// ---------------- big weight transpose+split (Wc1) ---------------------------
__global__ void wsplit_big_kernel(const float* __restrict__ W) {
    __shared__ float t[64][33];
    const int k0 = blockIdx.x * 64, n0 = blockIdx.y * 32;
    const int tx = threadIdx.x, ty = threadIdx.y;
    #pragma unroll
    for (int i = ty; i < 64; i += 8)
        t[i][tx] = W[(size_t)(k0 + i) * EDIM + n0 + tx];
    __syncthreads();
    #pragma unroll
    for (int i = ty; i < 32; i += 8) {
        const float v0 = t[2 * tx][i], v1 = t[2 * tx + 1][i];
        const __nv_bfloat16 h0 = __float2bfloat16(v0);
        const __nv_bfloat16 h1 = __float2bfloat16(v1);
        const size_t o = (size_t)(n0 + i) * D6 + k0 + 2 * tx;
        *(uint32_t*)&g_Wc1T_hi[o] = pack_bf16x2(v0, v1);
        *(uint32_t*)&g_Wc1T_lo[o] = pack_bf16x2(v0 - __bfloat162float(h0),
                                                v1 - __bfloat162float(h1));
    }
}

// ---------------- fused sequence-mean reductions -> bf16 hi/lo directly -----
__global__ void reduce_kernel(const float4* __restrict__ Q,
                              const float4* __restrict__ Vq,
                              const float4* __restrict__ A,
                              const float4* __restrict__ Va,
                              const int* __restrict__ qlen,
                              const int* __restrict__ alen) {
    const int b = blockIdx.x;
    const int which = blockIdx.y;
    const int d4 = threadIdx.x;
    const int stride = BATCH * (D2 / 4);

    const float4* p;
    int L;
    if (which == 0)      { L = max(qlen[b], 1); p = Q  + b * (D2 / 4) + d4; }
    else if (which == 1) { L = TV;              p = Vq + b * (D2 / 4) + d4; }
    else if (which == 2) { L = max(alen[b], 1); p = A  + b * (D2 / 4) + d4; }
    else                 { L = TV;              p = Va + b * (D2 / 4) + d4; }

    float4 acc = make_float4(0.f, 0.f, 0.f, 0.f);
    #pragma unroll 8
    for (int t = 0; t < L; t++) {
        float4 v = p[t * stride];
        acc.x += v.x; acc.y += v.y; acc.z += v.z; acc.w += v.w;
    }
    const float inv = 1.f / (float)L;
    float vals[4] = {acc.x * inv, acc.y * inv, acc.z * inv, acc.w * inv};

    size_t base;
    __nv_bfloat16 *hi, *lo;
    if (which == 0)      { hi = g_qm_hi; lo = g_qm_lo; base = (size_t)b * D2 + 4 * d4; }
    else if (which == 1) { hi = g_X_hi;  lo = g_X_lo;  base = (size_t)b * D6 + EDIM + 4 * d4; }
    else if (which == 2) { hi = g_am_hi; lo = g_am_lo; base = (size_t)b * D2 + 4 * d4; }
    else                 { hi = g_X_hi;  lo = g_X_lo;  base = (size_t)b * D6 + 2048 + 4 * d4; }
    #pragma unroll
    for (int j = 0; j < 4; j++) split_store(hi, lo, base + j, vals[j]);
}

// ---------------- split-bf16 GEMM: cp.async 2-stage ring (occupancy) --------
// BM=64, BN=32, 4 warps (32x16 warp tiles). Fragment addressing as R11/R12.
// MODE 0: z=0: qm@WqT -> X[:,0:512); z=1: am@WaT -> X[:,1536:2048) (split-stored)
// MODE 2: X@Wc1T + bias + ELU -> g_h (fp32)
template <int MODE>
__global__ __launch_bounds__(128)
void gemm_mma(const float* __restrict__ bias0, const float* __restrict__ bias1) {
    constexpr int OA_L = 64 * ROWB;           // 5120
    constexpr int OB_H = 2 * 64 * ROWB;       // 10240
    constexpr int OB_L = OB_H + 32 * ROWB;    // 12800
    constexpr int SS   = OB_L + 32 * ROWB;    // 15360 per stage
    __shared__ __align__(16) unsigned char smem[2 * SS];   // 30720 -> ~6 CTAs/SM

    const int tid = threadIdx.x;
    const int w = tid >> 5, l = tid & 31;
    const int wm = w & 1, wn = w >> 1;
    const int g = l >> 2, tg = l & 3;

    const __nv_bfloat16 *Ahi, *Alo, *Bhi, *Blo;
    const float* bias;
    int ldv, niter, colbase;
    if (MODE == 2) {
        Ahi = g_X_hi; Alo = g_X_lo; Bhi = g_Wc1T_hi; Blo = g_Wc1T_lo;
        bias = bias0; colbase = 0;
        ldv = D6 / 8; niter = D6 / 32;
    } else {
        if (blockIdx.z == 0) {
            Ahi = g_qm_hi; Alo = g_qm_lo; Bhi = g_WqT_hi; Blo = g_WqT_lo;
            bias = bias0; colbase = 0;
        } else {
            Ahi = g_am_hi; Alo = g_am_lo; Bhi = g_WaT_hi; Blo = g_WaT_lo;
            bias = bias1; colbase = 3 * EDIM;
        }
        ldv = D2 / 8; niter = D2 / 32;
    }

    const int bm = blockIdx.y * 64, bn = blockIdx.x * 32;
    const uint4* gAhi = (const uint4*)Ahi + (size_t)bm * ldv;
    const uint4* gAlo = (const uint4*)Alo + (size_t)bm * ldv;
    const uint4* gBhi = (const uint4*)Bhi + (size_t)bn * ldv;
    const uint4* gBlo = (const uint4*)Blo + (size_t)bn * ldv;

    const uint32_t S = smem_u32(smem);
    const int aRow = l & 15, aC = (l >> 4) * 16;
    const int bRow = ((l >> 4) & 1) * 8 + (l & 7), bC = ((l >> 3) & 1) * 16;
    const uint32_t aOffH = (wm * 32 + aRow) * ROWB + aC;
    const uint32_t aOffL = aOffH + OA_L;
    const uint32_t bOffH = OB_H + (wn * 16 + bRow) * ROWB + bC;
    const uint32_t bOffL = bOffH + (OB_L - OB_H);

    // copy mapping: A 64 rows x 4 segs (2 cp/thread per half); B 32 rows x 4
    const int cr0 = tid >> 2, cs0 = tid & 3;   // rows 0..31
    const int cr1 = cr0 + 32;                  // rows 32..63
    const uint32_t dA0 = cr0 * ROWB + cs0 * 16;
    const uint32_t dA1 = cr1 * ROWB + cs0 * 16;
    const uint32_t dB0 = OB_H + cr0 * ROWB + cs0 * 16;

    float c[2][2][4] = {};

    #define ISSUE_STAGE(slot, kv) do {                                        \
        const uint32_t D = S + (slot) * SS;                                   \
        CP16(D + dA0,          gAhi + cr0 * ldv + (kv) + cs0);                \
        CP16(D + dA1,          gAhi + cr1 * ldv + (kv) + cs0);                \
        CP16(D + dA0 + OA_L,   gAlo + cr0 * ldv + (kv) + cs0);                \
        CP16(D + dA1 + OA_L,   gAlo + cr1 * ldv + (kv) + cs0);                \
        CP16(D + dB0,          gBhi + cr0 * ldv + (kv) + cs0);                \
        CP16(D + dB0 + (OB_L - OB_H), gBlo + cr0 * ldv + (kv) + cs0);         \
        CP_COMMIT();                                                          \
    } while (0)

    ISSUE_STAGE(0, 0);
    ISSUE_STAGE(1, 4);

    for (int it = 0; it < niter; it++) {
        const int slot = it & 1;
        CP_WAIT1();                 // stage[slot] complete (other still in flight)
        __syncthreads();

        const uint32_t B = S + slot * SS;
        #pragma unroll
        for (int ks = 0; ks < 2; ks++) {
            const int kb = ks * 32;
            uint32_t ah[2][4], al[2][4], bh[4], bl[4];
            #pragma unroll
            for (int mt = 0; mt < 2; mt++) {
                ldmat4(ah[mt], B + aOffH + mt * (16 * ROWB) + kb);
                ldmat4(al[mt], B + aOffL + mt * (16 * ROWB) + kb);
            }
            ldmat4(bh, B + bOffH + kb);
            ldmat4(bl, B + bOffL + kb);
            #pragma unroll
            for (int mt = 0; mt < 2; mt++)
                #pragma unroll
                for (int h = 0; h < 2; h++) {
                    float* acc = c[mt][h];
                    mma_bf16(acc, ah[mt], bh[h * 2], bh[h * 2 + 1]);
                    mma_bf16(acc, al[mt], bh[h * 2], bh[h * 2 + 1]);
                    mma_bf16(acc, ah[mt], bl[h * 2], bl[h * 2 + 1]);
                }
        }
        __syncthreads();            // all warps done reading stage[slot]
        if (it + 2 < niter)
            ISSUE_STAGE(slot, (it + 2) * 4);
    }
    #undef ISSUE_STAGE

    #pragma unroll
    for (int mt = 0; mt < 2; mt++) {
        #pragma unroll
        for (int h = 0; h < 2; h++) {
            const int col = bn + wn * 16 + h * 8 + tg * 2;
            const float b0v = bias[col], b1v = bias[col + 1];
            const int r0 = bm + wm * 32 + mt * 16 + g;
            float v00 = c[mt][h][0] + b0v;
            float v01 = c[mt][h][1] + b1v;
            float v10 = c[mt][h][2] + b0v;
            float v11 = c[mt][h][3] + b1v;
            if (MODE == 2) {
                if (v00 <= 0.f) v00 = expm1f(v00);
                if (v01 <= 0.f) v01 = expm1f(v01);
                if (v10 <= 0.f) v10 = expm1f(v10);
                if (v11 <= 0.f) v11 = expm1f(v11);
                g_h[(size_t)r0 * EDIM + col]           = v00;
                g_h[(size_t)r0 * EDIM + col + 1]       = v01;
                g_h[(size_t)(r0 + 8) * EDIM + col]     = v10;
                g_h[(size_t)(r0 + 8) * EDIM + col + 1] = v11;
            } else {
                const size_t base0 = (size_t)r0 * D6 + colbase + col;
                const size_t base1 = (size_t)(r0 + 8) * D6 + colbase + col;
                split_store(g_X_hi, g_X_lo, base0, v00);
                split_store(g_X_hi, g_X_lo, base0 + 1, v01);
                split_store(g_X_hi, g_X_lo, base1, v10);
                split_store(g_X_hi, g_X_lo, base1 + 1, v11);
            }
        }
    }
}

// ---------------- BN batch stats --------------------------------------------
__global__ void bn_stats_kernel() {
    const int r0 = blockIdx.x * 64;
    for (int c = threadIdx.x; c < EDIM; c += blockDim.x) {
        float s = 0.f, s2 = 0.f;
        #pragma unroll 8
        for (int r = 0; r < 64; r++) {
            float v = g_h[(size_t)(r0 + r) * EDIM + c];
            s += v; s2 += v * v;
        }
        atomicAdd(&g_sum[c], s);
        atomicAdd(&g_sumsq[c], s2);
    }
}

// ---------------- fused BN-finalize + GEMV ----------------------------------
__global__ __launch_bounds__(256) void gemv_kernel(const float* __restrict__ gamma,
                                                   const float* __restrict__ beta,
                                                   const float* __restrict__ Wc2,
                                                   const float* __restrict__ bc2,
                                                   float* __restrict__ out) {
    __shared__ float wc[EDIM];
    __shared__ float red[256];
    __shared__ float cst_s;
    const int t = threadIdx.x;
    const float invB = 1.f / (float)BATCH;
    float part = 0.f;
    #pragma unroll
    for (int i = 0; i < 2; i++) {
        const int c = t + i * 256;
        const float mu  = g_sum[c] * invB;
        const float var = fmaxf(g_sumsq[c] * invB - mu * mu, 0.f);
        const float sc  = gamma[c] * rsqrtf(var + BN_EPS);
        const float w2  = Wc2[c];
        wc[c] = sc * w2;
        part += (beta[c] - mu * sc) * w2;
    }
    red[t] = part;
    __syncthreads();
    for (int off = 128; off > 0; off >>= 1) {
        if (t < off) red[t] += red[t + off];
        __syncthreads();
    }
    if (t == 0) cst_s = red[0] + bc2[0];
    __syncthreads();

    const int warp = t >> 5, lane = t & 31;
    const int b = blockIdx.x * 8 + warp;
    const float* hr = g_h + (size_t)b * EDIM;
    float s = 0.f;
    #pragma unroll
    for (int c = lane; c < EDIM; c += 32) s += hr[c] * wc[c];
    #pragma unroll
    for (int off = 16; off > 0; off >>= 1) s += __shfl_down_sync(0xffffffffu, s, off);
    if (lane == 0) out[b] = s + cst_s;
}

// ---------------- launcher --------------------------------------------------
extern "C" void kernel_launch(void* const* d_in, const int* in_sizes, int n_in,
                              void* d_out, int out_size) {
    const float* Q    = (const float*)d_in[0];
    const float* Vq   = (const float*)d_in[1];
    const float* Aa   = (const float*)d_in[2];
    const float* Va   = (const float*)d_in[3];
    const int*   qlen = (const int*)d_in[4];
    const int*   alen = (const int*)d_in[5];
    const float* Wq   = (const float*)d_in[6];
    const float* bq   = (const float*)d_in[7];
    const float* Wa   = (const float*)d_in[8];
    const float* ba   = (const float*)d_in[9];
    const float* Wc1  = (const float*)d_in[10];
    const float* bc1  = (const float*)d_in[11];
    const float* gam  = (const float*)d_in[12];
    const float* bet  = (const float*)d_in[13];
    const float* Wc2  = (const float*)d_in[14];
    const float* bc2  = (const float*)d_in[15];
    float* out = (float*)d_out;

    wsplit_small_kernel<<<dim3(D2 / 64, EDIM / 32, 2), dim3(32, 8)>>>(Wq, Wa);
    wsplit_big_kernel<<<dim3(D6 / 64, EDIM / 32), dim3(32, 8)>>>(Wc1);
    reduce_kernel<<<dim3(BATCH, 4), 256>>>((const float4*)Q, (const float4*)Vq,
                                           (const float4*)Aa, (const float4*)Va,
                                           qlen, alen);
    gemm_mma<0><<<dim3(EDIM / 32, BATCH / 64, 2), 128>>>(bq, ba);   // 640 CTAs
    gemm_mma<2><<<dim3(EDIM / 32, BATCH / 64), 128>>>(bc1, bc1);    // 320 CTAs
    bn_stats_kernel<<<BATCH / 64, 256>>>();
    gemv_kernel<<<BATCH / 8, 256>>>(gam, bet, Wc2, bc2, out);
}

// round 14
// speedup vs baseline: 1.0001x; 1.0001x over previous
#include <cuda_runtime.h>
#include <cuda_bf16.h>
#include <cstdint>
#include <math.h>

#define BATCH 1280
#define EDIM  512
#define D2    1024
#define D6    3072
#define TV    64
#define BN_EPS 1e-5f

#define ROWB 80              // padded smem row stride bytes (40 bf16)

// ---------------- device globals (scratch; zero-initialized) ----------------
__device__ __align__(16) float g_h [BATCH * EDIM];
__device__ __align__(16) __nv_bfloat16 g_qm_hi[BATCH * D2], g_qm_lo[BATCH * D2];
__device__ __align__(16) __nv_bfloat16 g_am_hi[BATCH * D2], g_am_lo[BATCH * D2];
__device__ __align__(16) __nv_bfloat16 g_X_hi[BATCH * D6],  g_X_lo[BATCH * D6];
__device__ __align__(16) __nv_bfloat16 g_WqT_hi[EDIM * D2],  g_WqT_lo[EDIM * D2];
__device__ __align__(16) __nv_bfloat16 g_WaT_hi[EDIM * D2],  g_WaT_lo[EDIM * D2];
__device__ __align__(16) __nv_bfloat16 g_Wc1T_hi[EDIM * D6], g_Wc1T_lo[EDIM * D6];
__device__ float g_sum[EDIM], g_sumsq[EDIM];

__device__ __forceinline__ void split_store(__nv_bfloat16* hi, __nv_bfloat16* lo,
                                            size_t idx, float v) {
    __nv_bfloat16 h = __float2bfloat16(v);
    hi[idx] = h;
    lo[idx] = __float2bfloat16(v - __bfloat162float(h));
}

__device__ __forceinline__ uint32_t pack_bf16x2(float a, float b) {
    __nv_bfloat16 ha = __float2bfloat16(a), hb = __float2bfloat16(b);
    uint16_t ua, ub;
    memcpy(&ua, &ha, 2); memcpy(&ub, &hb, 2);
    return (uint32_t)ua | ((uint32_t)ub << 16);
}

__device__ __forceinline__ uint32_t smem_u32(const void* p) {
    uint32_t a;
    asm("{ .reg .u64 t; cvta.to.shared.u64 t, %1; cvt.u32.u64 %0, t; }"
        : "=r"(a) : "l"(p));
    return a;
}

__device__ __forceinline__ void ldmat4(uint32_t* r, uint32_t addr) {
    asm volatile("ldmatrix.sync.aligned.m8n8.x4.shared.b16 {%0,%1,%2,%3}, [%4];"
                 : "=r"(r[0]), "=r"(r[1]), "=r"(r[2]), "=r"(r[3]) : "r"(addr));
}

__device__ __forceinline__ void mma_bf16(float* c, const uint32_t* a,
                                         uint32_t b0, uint32_t b1) {
    asm volatile(
        "mma.sync.aligned.m16n8k16.row.col.f32.bf16.bf16.f32 "
        "{%0,%1,%2,%3}, {%4,%5,%6,%7}, {%8,%9}, {%0,%1,%2,%3};"
        : "+f"(c[0]), "+f"(c[1]), "+f"(c[2]), "+f"(c[3])
        : "r"(a[0]), "r"(a[1]), "r"(a[2]), "r"(a[3]), "r"(b0), "r"(b1));
}

#define CP16(dst, src) \
    asm volatile("cp.async.cg.shared.global [%0], [%1], 16;" \
                 :: "r"(dst), "l"(src) : "memory")
#define CP_COMMIT() asm volatile("cp.async.commit_group;" ::: "memory")
#define CP_WAIT1()  asm volatile("cp.async.wait_group 1;" ::: "memory")

// ---------------- small weight transpose+split (Wq/Wa via z) + stats zero ---
__global__ void wsplit_small_kernel(const float* __restrict__ Wq,
                                    const float* __restrict__ Wa) {
    const int which = blockIdx.z;
    const float* W = which ? Wa : Wq;
    __nv_bfloat16* oh = which ? g_WaT_hi : g_WqT_hi;
    __nv_bfloat16* ol = which ? g_WaT_lo : g_WqT_lo;
    const int tid = threadIdx.y * 32 + threadIdx.x;
    if (which == 0 && blockIdx.x == 0 && blockIdx.y == 0) {
        g_sum[tid] = 0.f; g_sum[tid + 256] = 0.f;
        g_sumsq[tid] = 0.f; g_sumsq[tid + 256] = 0.f;
    }
    __shared__ float t[64][33];
    const int k0 = blockIdx.x * 64, n0 = blockIdx.y * 32;
    const int tx = threadIdx.x, ty = threadIdx.y;
    #pragma unroll
    for (int i = ty; i < 64; i += 8)
        t[i][tx] = W[(size_t)(k0 + i) * EDIM + n0 + tx];
    __syncthreads();
    #pragma unroll
    for (int i = ty; i < 32; i += 8) {
        const float v0 = t[2 * tx][i], v1 = t[2 * tx + 1][i];
        const __nv_bfloat16 h0 = __float2bfloat16(v0);
        const __nv_bfloat16 h1 = __float2bfloat16(v1);
        const size_t o = (size_t)(n0 + i) * D2 + k0 + 2 * tx;
        *(uint32_t*)&oh[o] = pack_bf16x2(v0, v1);
        *(uint32_t*)&ol[o] = pack_bf16x2(v0 - __bfloat162float(h0),
                                         v1 - __bfloat162float(h1));
    }
}

// ---------------- big weight transpose+split (Wc1) ---------------------------
__global__ void wsplit_big_kernel(const float* __restrict__ W) {
    __shared__ float t[64][33];
    const int k0 = blockIdx.x * 64, n0 = blockIdx.y * 32;
    const int tx = threadIdx.x, ty = threadIdx.y;
    #pragma unroll
    for (int i = ty; i < 64; i += 8)
        t[i][tx] = W[(size_t)(k0 + i) * EDIM + n0 + tx];
    __syncthreads();
    #pragma unroll
    for (int i = ty; i < 32; i += 8) {
        const float v0 = t[2 * tx][i], v1 = t[2 * tx + 1][i];
        const __nv_bfloat16 h0 = __float2bfloat16(v0);
        const __nv_bfloat16 h1 = __float2bfloat16(v1);
        const size_t o = (size_t)(n0 + i) * D6 + k0 + 2 * tx;
        *(uint32_t*)&g_Wc1T_hi[o] = pack_bf16x2(v0, v1);
        *(uint32_t*)&g_Wc1T_lo[o] = pack_bf16x2(v0 - __bfloat162float(h0),
                                                v1 - __bfloat162float(h1));
    }
}

// ---------------- fused sequence-mean reductions -> bf16 hi/lo directly -----
__global__ void reduce_kernel(const float4* __restrict__ Q,
                              const float4* __restrict__ Vq,
                              const float4* __restrict__ A,
                              const float4* __restrict__ Va,
                              const int* __restrict__ qlen,
                              const int* __restrict__ alen) {
    const int b = blockIdx.x;
    const int which = blockIdx.y;
    const int d4 = threadIdx.x;
    const int stride = BATCH * (D2 / 4);

    const float4* p;
    int L;
    if (which == 0)      { L = max(qlen[b], 1); p = Q  + b * (D2 / 4) + d4; }
    else if (which == 1) { L = TV;              p = Vq + b * (D2 / 4) + d4; }
    else if (which == 2) { L = max(alen[b], 1); p = A  + b * (D2 / 4) + d4; }
    else                 { L = TV;              p = Va + b * (D2 / 4) + d4; }

    float4 acc = make_float4(0.f, 0.f, 0.f, 0.f);
    #pragma unroll 8
    for (int t = 0; t < L; t++) {
        float4 v = p[t * stride];
        acc.x += v.x; acc.y += v.y; acc.z += v.z; acc.w += v.w;
    }
    const float inv = 1.f / (float)L;
    float vals[4] = {acc.x * inv, acc.y * inv, acc.z * inv, acc.w * inv};

    size_t base;
    __nv_bfloat16 *hi, *lo;
    if (which == 0)      { hi = g_qm_hi; lo = g_qm_lo; base = (size_t)b * D2 + 4 * d4; }
    else if (which == 1) { hi = g_X_hi;  lo = g_X_lo;  base = (size_t)b * D6 + EDIM + 4 * d4; }
    else if (which == 2) { hi = g_am_hi; lo = g_am_lo; base = (size_t)b * D2 + 4 * d4; }
    else                 { hi = g_X_hi;  lo = g_X_lo;  base = (size_t)b * D6 + 2048 + 4 * d4; }
    #pragma unroll
    for (int j = 0; j < 4; j++) split_store(hi, lo, base + j, vals[j]);
}

// ---------------- split-bf16 GEMM: cp.async 2-stage ring (occupancy) --------
// BM=64, BN=32, 4 warps (32x16 warp tiles). Fragment addressing as R11/R12.
// MODE 0: z=0: qm@WqT -> X[:,0:512); z=1: am@WaT -> X[:,1536:2048) (split-stored)
// MODE 2: X@Wc1T + bias + ELU -> g_h (fp32)
template <int MODE>
__global__ __launch_bounds__(128)
void gemm_mma(const float* __restrict__ bias0, const float* __restrict__ bias1) {
    constexpr int OA_L = 64 * ROWB;           // 5120
    constexpr int OB_H = 2 * 64 * ROWB;       // 10240
    constexpr int OB_L = OB_H + 32 * ROWB;    // 12800
    constexpr int SS   = OB_L + 32 * ROWB;    // 15360 per stage
    __shared__ __align__(16) unsigned char smem[2 * SS];   // 30720 -> ~6 CTAs/SM

    const int tid = threadIdx.x;
    const int w = tid >> 5, l = tid & 31;
    const int wm = w & 1, wn = w >> 1;
    const int g = l >> 2, tg = l & 3;

    const __nv_bfloat16 *Ahi, *Alo, *Bhi, *Blo;
    const float* bias;
    int ldv, niter, colbase;
    if (MODE == 2) {
        Ahi = g_X_hi; Alo = g_X_lo; Bhi = g_Wc1T_hi; Blo = g_Wc1T_lo;
        bias = bias0; colbase = 0;
        ldv = D6 / 8; niter = D6 / 32;
    } else {
        if (blockIdx.z == 0) {
            Ahi = g_qm_hi; Alo = g_qm_lo; Bhi = g_WqT_hi; Blo = g_WqT_lo;
            bias = bias0; colbase = 0;
        } else {
            Ahi = g_am_hi; Alo = g_am_lo; Bhi = g_WaT_hi; Blo = g_WaT_lo;
            bias = bias1; colbase = 3 * EDIM;
        }
        ldv = D2 / 8; niter = D2 / 32;
    }

    const int bm = blockIdx.y * 64, bn = blockIdx.x * 32;
    const uint4* gAhi = (const uint4*)Ahi + (size_t)bm * ldv;
    const uint4* gAlo = (const uint4*)Alo + (size_t)bm * ldv;
    const uint4* gBhi = (const uint4*)Bhi + (size_t)bn * ldv;
    const uint4* gBlo = (const uint4*)Blo + (size_t)bn * ldv;

    const uint32_t S = smem_u32(smem);
    const int aRow = l & 15, aC = (l >> 4) * 16;
    const int bRow = ((l >> 4) & 1) * 8 + (l & 7), bC = ((l >> 3) & 1) * 16;
    const uint32_t aOffH = (wm * 32 + aRow) * ROWB + aC;
    const uint32_t aOffL = aOffH + OA_L;
    const uint32_t bOffH = OB_H + (wn * 16 + bRow) * ROWB + bC;
    const uint32_t bOffL = bOffH + (OB_L - OB_H);

    // copy mapping: A 64 rows x 4 segs (2 cp/thread per half); B 32 rows x 4
    const int cr0 = tid >> 2, cs0 = tid & 3;   // rows 0..31
    const int cr1 = cr0 + 32;                  // rows 32..63
    const uint32_t dA0 = cr0 * ROWB + cs0 * 16;
    const uint32_t dA1 = cr1 * ROWB + cs0 * 16;
    const uint32_t dB0 = OB_H + cr0 * ROWB + cs0 * 16;

    float c[2][2][4] = {};

    #define ISSUE_STAGE(slot, kv) do {                                        \
        const uint32_t D = S + (slot) * SS;                                   \
        CP16(D + dA0,          gAhi + cr0 * ldv + (kv) + cs0);                \
        CP16(D + dA1,          gAhi + cr1 * ldv + (kv) + cs0);                \
        CP16(D + dA0 + OA_L,   gAlo + cr0 * ldv + (kv) + cs0);                \
        CP16(D + dA1 + OA_L,   gAlo + cr1 * ldv + (kv) + cs0);                \
        CP16(D + dB0,          gBhi + cr0 * ldv + (kv) + cs0);                \
        CP16(D + dB0 + (OB_L - OB_H), gBlo + cr0 * ldv + (kv) + cs0);         \
        CP_COMMIT();                                                          \
    } while (0)

    ISSUE_STAGE(0, 0);
    ISSUE_STAGE(1, 4);

    for (int it = 0; it < niter; it++) {
        const int slot = it & 1;
        CP_WAIT1();                 // stage[slot] complete (other still in flight)
        __syncthreads();

        const uint32_t B = S + slot * SS;
        #pragma unroll
        for (int ks = 0; ks < 2; ks++) {
            const int kb = ks * 32;
            uint32_t ah[2][4], al[2][4], bh[4], bl[4];
            #pragma unroll
            for (int mt = 0; mt < 2; mt++) {
                ldmat4(ah[mt], B + aOffH + mt * (16 * ROWB) + kb);
                ldmat4(al[mt], B + aOffL + mt * (16 * ROWB) + kb);
            }
            ldmat4(bh, B + bOffH + kb);
            ldmat4(bl, B + bOffL + kb);
            #pragma unroll
            for (int mt = 0; mt < 2; mt++)
                #pragma unroll
                for (int h = 0; h < 2; h++) {
                    float* acc = c[mt][h];
                    mma_bf16(acc, ah[mt], bh[h * 2], bh[h * 2 + 1]);
                    mma_bf16(acc, al[mt], bh[h * 2], bh[h * 2 + 1]);
                    mma_bf16(acc, ah[mt], bl[h * 2], bl[h * 2 + 1]);
                }
        }
        __syncthreads();            // all warps done reading stage[slot]
        if (it + 2 < niter)
            ISSUE_STAGE(slot, (it + 2) * 4);
    }
    #undef ISSUE_STAGE

    #pragma unroll
    for (int mt = 0; mt < 2; mt++) {
        #pragma unroll
        for (int h = 0; h < 2; h++) {
            const int col = bn + wn * 16 + h * 8 + tg * 2;
            const float b0v = bias[col], b1v = bias[col + 1];
            const int r0 = bm + wm * 32 + mt * 16 + g;
            float v00 = c[mt][h][0] + b0v;
            float v01 = c[mt][h][1] + b1v;
            float v10 = c[mt][h][2] + b0v;
            float v11 = c[mt][h][3] + b1v;
            if (MODE == 2) {
                if (v00 <= 0.f) v00 = expm1f(v00);
                if (v01 <= 0.f) v01 = expm1f(v01);
                if (v10 <= 0.f) v10 = expm1f(v10);
                if (v11 <= 0.f) v11 = expm1f(v11);
                g_h[(size_t)r0 * EDIM + col]           = v00;
                g_h[(size_t)r0 * EDIM + col + 1]       = v01;
                g_h[(size_t)(r0 + 8) * EDIM + col]     = v10;
                g_h[(size_t)(r0 + 8) * EDIM + col + 1] = v11;
            } else {
                const size_t base0 = (size_t)r0 * D6 + colbase + col;
                const size_t base1 = (size_t)(r0 + 8) * D6 + colbase + col;
                split_store(g_X_hi, g_X_lo, base0, v00);
                split_store(g_X_hi, g_X_lo, base0 + 1, v01);
                split_store(g_X_hi, g_X_lo, base1, v10);
                split_store(g_X_hi, g_X_lo, base1 + 1, v11);
            }
        }
    }
}

// ---------------- BN batch stats --------------------------------------------
__global__ void bn_stats_kernel() {
    const int r0 = blockIdx.x * 64;
    for (int c = threadIdx.x; c < EDIM; c += blockDim.x) {
        float s = 0.f, s2 = 0.f;
        #pragma unroll 8
        for (int r = 0; r < 64; r++) {
            float v = g_h[(size_t)(r0 + r) * EDIM + c];
            s += v; s2 += v * v;
        }
        atomicAdd(&g_sum[c], s);
        atomicAdd(&g_sumsq[c], s2);
    }
}

// ---------------- fused BN-finalize + GEMV ----------------------------------
__global__ __launch_bounds__(256) void gemv_kernel(const float* __restrict__ gamma,
                                                   const float* __restrict__ beta,
                                                   const float* __restrict__ Wc2,
                                                   const float* __restrict__ bc2,
                                                   float* __restrict__ out) {
    __shared__ float wc[EDIM];
    __shared__ float red[256];
    __shared__ float cst_s;
    const int t = threadIdx.x;
    const float invB = 1.f / (float)BATCH;
    float part = 0.f;
    #pragma unroll
    for (int i = 0; i < 2; i++) {
        const int c = t + i * 256;
        const float mu  = g_sum[c] * invB;
        const float var = fmaxf(g_sumsq[c] * invB - mu * mu, 0.f);
        const float sc  = gamma[c] * rsqrtf(var + BN_EPS);
        const float w2  = Wc2[c];
        wc[c] = sc * w2;
        part += (beta[c] - mu * sc) * w2;
    }
    red[t] = part;
    __syncthreads();
    for (int off = 128; off > 0; off >>= 1) {
        if (t < off) red[t] += red[t + off];
        __syncthreads();
    }
    if (t == 0) cst_s = red[0] + bc2[0];
    __syncthreads();

    const int warp = t >> 5, lane = t & 31;
    const int b = blockIdx.x * 8 + warp;
    const float* hr = g_h + (size_t)b * EDIM;
    float s = 0.f;
    #pragma unroll
    for (int c = lane; c < EDIM; c += 32) s += hr[c] * wc[c];
    #pragma unroll
    for (int off = 16; off > 0; off >>= 1) s += __shfl_down_sync(0xffffffffu, s, off);
    if (lane == 0) out[b] = s + cst_s;
}

// ---------------- launcher --------------------------------------------------
extern "C" void kernel_launch(void* const* d_in, const int* in_sizes, int n_in,
                              void* d_out, int out_size) {
    const float* Q    = (const float*)d_in[0];
    const float* Vq   = (const float*)d_in[1];
    const float* Aa   = (const float*)d_in[2];
    const float* Va   = (const float*)d_in[3];
    const int*   qlen = (const int*)d_in[4];
    const int*   alen = (const int*)d_in[5];
    const float* Wq   = (const float*)d_in[6];
    const float* bq   = (const float*)d_in[7];
    const float* Wa   = (const float*)d_in[8];
    const float* ba   = (const float*)d_in[9];
    const float* Wc1  = (const float*)d_in[10];
    const float* bc1  = (const float*)d_in[11];
    const float* gam  = (const float*)d_in[12];
    const float* bet  = (const float*)d_in[13];
    const float* Wc2  = (const float*)d_in[14];
    const float* bc2  = (const float*)d_in[15];
    float* out = (float*)d_out;

    wsplit_small_kernel<<<dim3(D2 / 64, EDIM / 32, 2), dim3(32, 8)>>>(Wq, Wa);
    wsplit_big_kernel<<<dim3(D6 / 64, EDIM / 32), dim3(32, 8)>>>(Wc1);
    reduce_kernel<<<dim3(BATCH, 4), 256>>>((const float4*)Q, (const float4*)Vq,
                                           (const float4*)Aa, (const float4*)Va,
                                           qlen, alen);
    gemm_mma<0><<<dim3(EDIM / 32, BATCH / 64, 2), 128>>>(bq, ba);   // 640 CTAs
    gemm_mma<2><<<dim3(EDIM / 32, BATCH / 64), 128>>>(bc1, bc1);    // 320 CTAs
    bn_stats_kernel<<<BATCH / 64, 256>>>();
    gemv_kernel<<<BATCH / 8, 256>>>(gam, bet, Wc2, bc2, out);
}

// round 15
// speedup vs baseline: 1.0153x; 1.0152x over previous
#include <cuda_runtime.h>
#include <cuda_bf16.h>
#include <cstdint>
#include <math.h>

#define BATCH 1280
#define EDIM  512
#define D2    1024
#define D6    3072
#define TV    64
#define BN_EPS 1e-5f

#define ROWB 80              // padded smem row stride bytes (40 bf16)

// ---------------- device globals (scratch; zero-initialized) ----------------
__device__ __align__(16) float g_h [BATCH * EDIM];
__device__ __align__(16) __nv_bfloat16 g_qm_hi[BATCH * D2], g_qm_lo[BATCH * D2];
__device__ __align__(16) __nv_bfloat16 g_am_hi[BATCH * D2], g_am_lo[BATCH * D2];
__device__ __align__(16) __nv_bfloat16 g_X_hi[BATCH * D6],  g_X_lo[BATCH * D6];
__device__ __align__(16) __nv_bfloat16 g_WqT_hi[EDIM * D2],  g_WqT_lo[EDIM * D2];
__device__ __align__(16) __nv_bfloat16 g_WaT_hi[EDIM * D2],  g_WaT_lo[EDIM * D2];
__device__ __align__(16) __nv_bfloat16 g_Wc1T_hi[EDIM * D6], g_Wc1T_lo[EDIM * D6];
__device__ float g_sum[EDIM], g_sumsq[EDIM];

__device__ __forceinline__ void split_store(__nv_bfloat16* hi, __nv_bfloat16* lo,
                                            size_t idx, float v) {
    __nv_bfloat16 h = __float2bfloat16(v);
    hi[idx] = h;
    lo[idx] = __float2bfloat16(v - __bfloat162float(h));
}

__device__ __forceinline__ uint32_t pack_bf16x2(float a, float b) {
    __nv_bfloat16 ha = __float2bfloat16(a), hb = __float2bfloat16(b);
    uint16_t ua, ub;
    memcpy(&ua, &ha, 2); memcpy(&ub, &hb, 2);
    return (uint32_t)ua | ((uint32_t)ub << 16);
}

__device__ __forceinline__ uint32_t smem_u32(const void* p) {
    uint32_t a;
    asm("{ .reg .u64 t; cvta.to.shared.u64 t, %1; cvt.u32.u64 %0, t; }"
        : "=r"(a) : "l"(p));
    return a;
}

__device__ __forceinline__ void ldmat4(uint32_t* r, uint32_t addr) {
    asm volatile("ldmatrix.sync.aligned.m8n8.x4.shared.b16 {%0,%1,%2,%3}, [%4];"
                 : "=r"(r[0]), "=r"(r[1]), "=r"(r[2]), "=r"(r[3]) : "r"(addr));
}

__device__ __forceinline__ void mma_bf16(float* c, const uint32_t* a,
                                         uint32_t b0, uint32_t b1) {
    asm volatile(
        "mma.sync.aligned.m16n8k16.row.col.f32.bf16.bf16.f32 "
        "{%0,%1,%2,%3}, {%4,%5,%6,%7}, {%8,%9}, {%0,%1,%2,%3};"
        : "+f"(c[0]), "+f"(c[1]), "+f"(c[2]), "+f"(c[3])
        : "r"(a[0]), "r"(a[1]), "r"(a[2]), "r"(a[3]), "r"(b0), "r"(b1));
}

#define CP16(dst, src) \
    asm volatile("cp.async.cg.shared.global [%0], [%1], 16;" \
                 :: "r"(dst), "l"(src) : "memory")
#define CP_COMMIT() asm volatile("cp.async.commit_group;" ::: "memory")
#define CP_WAIT1()  asm volatile("cp.async.wait_group 1;" ::: "memory")

// ---------------- small weight transpose+split (Wq/Wa via z) + stats zero ---
__global__ void wsplit_small_kernel(const float* __restrict__ Wq,
                                    const float* __restrict__ Wa) {
    const int which = blockIdx.z;
    const float* W = which ? Wa : Wq;
    __nv_bfloat16* oh = which ? g_WaT_hi : g_WqT_hi;
    __nv_bfloat16* ol = which ? g_WaT_lo : g_WqT_lo;
    const int tid = threadIdx.y * 32 + threadIdx.x;
    if (which == 0 && blockIdx.x == 0 && blockIdx.y == 0) {
        g_sum[tid] = 0.f; g_sum[tid + 256] = 0.f;
        g_sumsq[tid] = 0.f; g_sumsq[tid + 256] = 0.f;
    }
    __shared__ float t[64][33];
    const int k0 = blockIdx.x * 64, n0 = blockIdx.y * 32;
    const int tx = threadIdx.x, ty = threadIdx.y;
    #pragma unroll
    for (int i = ty; i < 64; i += 8)
        t[i][tx] = W[(size_t)(k0 + i) * EDIM + n0 + tx];
    __syncthreads();
    #pragma unroll
    for (int i = ty; i < 32; i += 8) {
        const float v0 = t[2 * tx][i], v1 = t[2 * tx + 1][i];
        const __nv_bfloat16 h0 = __float2bfloat16(v0);
        const __nv_bfloat16 h1 = __float2bfloat16(v1);
        const size_t o = (size_t)(n0 + i) * D2 + k0 + 2 * tx;
        *(uint32_t*)&oh[o] = pack_bf16x2(v0, v1);
        *(uint32_t*)&ol[o] = pack_bf16x2(v0 - __bfloat162float(h0),
                                         v1 - __bfloat162float(h1));
    }
}

// ---------------- big weight transpose+split (Wc1) ---------------------------
__global__ void wsplit_big_kernel(const float* __restrict__ W) {
    __shared__ float t[64][33];
    const int k0 = blockIdx.x * 64, n0 = blockIdx.y * 32;
    const int tx = threadIdx.x, ty = threadIdx.y;
    #pragma unroll
    for (int i = ty; i < 64; i += 8)
        t[i][tx] = W[(size_t)(k0 + i) * EDIM + n0 + tx];
    __syncthreads();
    #pragma unroll
    for (int i = ty; i < 32; i += 8) {
        const float v0 = t[2 * tx][i], v1 = t[2 * tx + 1][i];
        const __nv_bfloat16 h0 = __float2bfloat16(v0);
        const __nv_bfloat16 h1 = __float2bfloat16(v1);
        const size_t o = (size_t)(n0 + i) * D6 + k0 + 2 * tx;
        *(uint32_t*)&g_Wc1T_hi[o] = pack_bf16x2(v0, v1);
        *(uint32_t*)&g_Wc1T_lo[o] = pack_bf16x2(v0 - __bfloat162float(h0),
                                                v1 - __bfloat162float(h1));
    }
}

// ---------------- fused sequence-mean reductions -> bf16 hi/lo directly -----
__global__ void reduce_kernel(const float4* __restrict__ Q,
                              const float4* __restrict__ Vq,
                              const float4* __restrict__ A,
                              const float4* __restrict__ Va,
                              const int* __restrict__ qlen,
                              const int* __restrict__ alen) {
    const int b = blockIdx.x;
    const int which = blockIdx.y;
    const int d4 = threadIdx.x;
    const int stride = BATCH * (D2 / 4);

    const float4* p;
    int L;
    if (which == 0)      { L = max(qlen[b], 1); p = Q  + b * (D2 / 4) + d4; }
    else if (which == 1) { L = TV;              p = Vq + b * (D2 / 4) + d4; }
    else if (which == 2) { L = max(alen[b], 1); p = A  + b * (D2 / 4) + d4; }
    else                 { L = TV;              p = Va + b * (D2 / 4) + d4; }

    float4 acc = make_float4(0.f, 0.f, 0.f, 0.f);
    #pragma unroll 8
    for (int t = 0; t < L; t++) {
        float4 v = p[t * stride];
        acc.x += v.x; acc.y += v.y; acc.z += v.z; acc.w += v.w;
    }
    const float inv = 1.f / (float)L;
    float vals[4] = {acc.x * inv, acc.y * inv, acc.z * inv, acc.w * inv};

    size_t base;
    __nv_bfloat16 *hi, *lo;
    if (which == 0)      { hi = g_qm_hi; lo = g_qm_lo; base = (size_t)b * D2 + 4 * d4; }
    else if (which == 1) { hi = g_X_hi;  lo = g_X_lo;  base = (size_t)b * D6 + EDIM + 4 * d4; }
    else if (which == 2) { hi = g_am_hi; lo = g_am_lo; base = (size_t)b * D2 + 4 * d4; }
    else                 { hi = g_X_hi;  lo = g_X_lo;  base = (size_t)b * D6 + 2048 + 4 * d4; }
    #pragma unroll
    for (int j = 0; j < 4; j++) split_store(hi, lo, base + j, vals[j]);
}

// ---------------- split-bf16 GEMM: cp.async 3-stage ring, 1 barrier/iter ----
// BM=64, BN=32, 4 warps (32x16 warp tiles). Fragment addressing as R11/R12.
// Slot written at iter it ((it+2)%3) was last READ at iter it-1; the top
// barrier of iter it orders all warps past that compute -> no trailing barrier.
// MODE 0: z=0: qm@WqT -> X[:,0:512); z=1: am@WaT -> X[:,1536:2048) (split-stored)
// MODE 2: X@Wc1T + bias + ELU -> g_h (fp32)
template <int MODE>
__global__ __launch_bounds__(128)
void gemm_mma(const float* __restrict__ bias0, const float* __restrict__ bias1) {
    constexpr int OA_L = 64 * ROWB;           // 5120
    constexpr int OB_H = 2 * 64 * ROWB;       // 10240
    constexpr int OB_L = OB_H + 32 * ROWB;    // 12800
    constexpr int SS   = OB_L + 32 * ROWB;    // 15360 per stage
    __shared__ __align__(16) unsigned char smem[3 * SS];   // 46080 < 48K

    const int tid = threadIdx.x;
    const int w = tid >> 5, l = tid & 31;
    const int wm = w & 1, wn = w >> 1;
    const int g = l >> 2, tg = l & 3;

    const __nv_bfloat16 *Ahi, *Alo, *Bhi, *Blo;
    const float* bias;
    int ldv, niter, colbase;
    if (MODE == 2) {
        Ahi = g_X_hi; Alo = g_X_lo; Bhi = g_Wc1T_hi; Blo = g_Wc1T_lo;
        bias = bias0; colbase = 0;
        ldv = D6 / 8; niter = D6 / 32;
    } else {
        if (blockIdx.z == 0) {
            Ahi = g_qm_hi; Alo = g_qm_lo; Bhi = g_WqT_hi; Blo = g_WqT_lo;
            bias = bias0; colbase = 0;
        } else {
            Ahi = g_am_hi; Alo = g_am_lo; Bhi = g_WaT_hi; Blo = g_WaT_lo;
            bias = bias1; colbase = 3 * EDIM;
        }
        ldv = D2 / 8; niter = D2 / 32;
    }

    const int bm = blockIdx.y * 64, bn = blockIdx.x * 32;
    const uint4* gAhi = (const uint4*)Ahi + (size_t)bm * ldv;
    const uint4* gAlo = (const uint4*)Alo + (size_t)bm * ldv;
    const uint4* gBhi = (const uint4*)Bhi + (size_t)bn * ldv;
    const uint4* gBlo = (const uint4*)Blo + (size_t)bn * ldv;

    const uint32_t S = smem_u32(smem);
    const int aRow = l & 15, aC = (l >> 4) * 16;
    const int bRow = ((l >> 4) & 1) * 8 + (l & 7), bC = ((l >> 3) & 1) * 16;
    const uint32_t aOffH = (wm * 32 + aRow) * ROWB + aC;
    const uint32_t aOffL = aOffH + OA_L;
    const uint32_t bOffH = OB_H + (wn * 16 + bRow) * ROWB + bC;
    const uint32_t bOffL = bOffH + (OB_L - OB_H);

    // copy mapping: A 64 rows x 4 segs (2 cp/thread per half); B 32 rows x 4
    const int cr0 = tid >> 2, cs0 = tid & 3;   // rows 0..31
    const int cr1 = cr0 + 32;                  // rows 32..63
    const uint32_t dA0 = cr0 * ROWB + cs0 * 16;
    const uint32_t dA1 = cr1 * ROWB + cs0 * 16;
    const uint32_t dB0 = OB_H + cr0 * ROWB + cs0 * 16;

    float c[2][2][4] = {};

    #define ISSUE_STAGE(slot, kv) do {                                        \
        const uint32_t D = S + (slot) * SS;                                   \
        CP16(D + dA0,          gAhi + cr0 * ldv + (kv) + cs0);                \
        CP16(D + dA1,          gAhi + cr1 * ldv + (kv) + cs0);                \
        CP16(D + dA0 + OA_L,   gAlo + cr0 * ldv + (kv) + cs0);                \
        CP16(D + dA1 + OA_L,   gAlo + cr1 * ldv + (kv) + cs0);                \
        CP16(D + dB0,          gBhi + cr0 * ldv + (kv) + cs0);                \
        CP16(D + dB0 + (OB_L - OB_H), gBlo + cr0 * ldv + (kv) + cs0);         \
        CP_COMMIT();                                                          \
    } while (0)

    ISSUE_STAGE(0, 0);
    ISSUE_STAGE(1, 4);

    int slot = 0, nslot = 2;
    for (int it = 0; it < niter; it++) {
        CP_WAIT1();                 // stage[slot] landed (newest may be in flight)
        __syncthreads();            // also orders prior iter's reads of nslot

        if (it + 2 < niter) {
            ISSUE_STAGE(nslot, (it + 2) * 4);
            nslot = (nslot == 2) ? 0 : nslot + 1;
        }

        const uint32_t B = S + slot * SS;
        slot = (slot == 2) ? 0 : slot + 1;
        #pragma unroll
        for (int ks = 0; ks < 2; ks++) {
            const int kb = ks * 32;
            uint32_t ah[2][4], al[2][4], bh[4], bl[4];
            #pragma unroll
            for (int mt = 0; mt < 2; mt++) {
                ldmat4(ah[mt], B + aOffH + mt * (16 * ROWB) + kb);
                ldmat4(al[mt], B + aOffL + mt * (16 * ROWB) + kb);
            }
            ldmat4(bh, B + bOffH + kb);
            ldmat4(bl, B + bOffL + kb);
            #pragma unroll
            for (int mt = 0; mt < 2; mt++)
                #pragma unroll
                for (int h = 0; h < 2; h++) {
                    float* acc = c[mt][h];
                    mma_bf16(acc, ah[mt], bh[h * 2], bh[h * 2 + 1]);
                    mma_bf16(acc, al[mt], bh[h * 2], bh[h * 2 + 1]);
                    mma_bf16(acc, ah[mt], bl[h * 2], bl[h * 2 + 1]);
                }
        }
        // no trailing barrier: next iter's top barrier provides the ordering
    }
    #undef ISSUE_STAGE

    #pragma unroll
    for (int mt = 0; mt < 2; mt++) {
        #pragma unroll
        for (int h = 0; h < 2; h++) {
            const int col = bn + wn * 16 + h * 8 + tg * 2;
            const float b0v = bias[col], b1v = bias[col + 1];
            const int r0 = bm + wm * 32 + mt * 16 + g;
            float v00 = c[mt][h][0] + b0v;
            float v01 = c[mt][h][1] + b1v;
            float v10 = c[mt][h][2] + b0v;
            float v11 = c[mt][h][3] + b1v;
            if (MODE == 2) {
                if (v00 <= 0.f) v00 = expm1f(v00);
                if (v01 <= 0.f) v01 = expm1f(v01);
                if (v10 <= 0.f) v10 = expm1f(v10);
                if (v11 <= 0.f) v11 = expm1f(v11);
                g_h[(size_t)r0 * EDIM + col]           = v00;
                g_h[(size_t)r0 * EDIM + col + 1]       = v01;
                g_h[(size_t)(r0 + 8) * EDIM + col]     = v10;
                g_h[(size_t)(r0 + 8) * EDIM + col + 1] = v11;
            } else {
                const size_t base0 = (size_t)r0 * D6 + colbase + col;
                const size_t base1 = (size_t)(r0 + 8) * D6 + colbase + col;
                split_store(g_X_hi, g_X_lo, base0, v00);
                split_store(g_X_hi, g_X_lo, base0 + 1, v01);
                split_store(g_X_hi, g_X_lo, base1, v10);
                split_store(g_X_hi, g_X_lo, base1 + 1, v11);
            }
        }
    }
}

// ---------------- BN batch stats --------------------------------------------
__global__ void bn_stats_kernel() {
    const int r0 = blockIdx.x * 64;
    for (int c = threadIdx.x; c < EDIM; c += blockDim.x) {
        float s = 0.f, s2 = 0.f;
        #pragma unroll 8
        for (int r = 0; r < 64; r++) {
            float v = g_h[(size_t)(r0 + r) * EDIM + c];
            s += v; s2 += v * v;
        }
        atomicAdd(&g_sum[c], s);
        atomicAdd(&g_sumsq[c], s2);
    }
}

// ---------------- fused BN-finalize + GEMV ----------------------------------
__global__ __launch_bounds__(256) void gemv_kernel(const float* __restrict__ gamma,
                                                   const float* __restrict__ beta,
                                                   const float* __restrict__ Wc2,
                                                   const float* __restrict__ bc2,
                                                   float* __restrict__ out) {
    __shared__ float wc[EDIM];
    __shared__ float red[256];
    __shared__ float cst_s;
    const int t = threadIdx.x;
    const float invB = 1.f / (float)BATCH;
    float part = 0.f;
    #pragma unroll
    for (int i = 0; i < 2; i++) {
        const int c = t + i * 256;
        const float mu  = g_sum[c] * invB;
        const float var = fmaxf(g_sumsq[c] * invB - mu * mu, 0.f);
        const float sc  = gamma[c] * rsqrtf(var + BN_EPS);
        const float w2  = Wc2[c];
        wc[c] = sc * w2;
        part += (beta[c] - mu * sc) * w2;
    }
    red[t] = part;
    __syncthreads();
    for (int off = 128; off > 0; off >>= 1) {
        if (t < off) red[t] += red[t + off];
        __syncthreads();
    }
    if (t == 0) cst_s = red[0] + bc2[0];
    __syncthreads();

    const int warp = t >> 5, lane = t & 31;
    const int b = blockIdx.x * 8 + warp;
    const float* hr = g_h + (size_t)b * EDIM;
    float s = 0.f;
    #pragma unroll
    for (int c = lane; c < EDIM; c += 32) s += hr[c] * wc[c];
    #pragma unroll
    for (int off = 16; off > 0; off >>= 1) s += __shfl_down_sync(0xffffffffu, s, off);
    if (lane == 0) out[b] = s + cst_s;
}

// ---------------- launcher --------------------------------------------------
extern "C" void kernel_launch(void* const* d_in, const int* in_sizes, int n_in,
                              void* d_out, int out_size) {
    const float* Q    = (const float*)d_in[0];
    const float* Vq   = (const float*)d_in[1];
    const float* Aa   = (const float*)d_in[2];
    const float* Va   = (const float*)d_in[3];
    const int*   qlen = (const int*)d_in[4];
    const int*   alen = (const int*)d_in[5];
    const float* Wq   = (const float*)d_in[6];
    const float* bq   = (const float*)d_in[7];
    const float* Wa   = (const float*)d_in[8];
    const float* ba   = (const float*)d_in[9];
    const float* Wc1  = (const float*)d_in[10];
    const float* bc1  = (const float*)d_in[11];
    const float* gam  = (const float*)d_in[12];
    const float* bet  = (const float*)d_in[13];
    const float* Wc2  = (const float*)d_in[14];
    const float* bc2  = (const float*)d_in[15];
    float* out = (float*)d_out;

    // raise the smem carveout so 46KB/CTA admits ~4 CTAs/SM (one-time, cached
    // by the driver; legal under graph capture — no alloc, no sync)
    static bool configured = false;
    if (!configured) {
        cudaFuncSetAttribute(gemm_mma<0>,
                             cudaFuncAttributePreferredSharedMemoryCarveout, 100);
        cudaFuncSetAttribute(gemm_mma<2>,
                             cudaFuncAttributePreferredSharedMemoryCarveout, 100);
        configured = true;
    }

    wsplit_small_kernel<<<dim3(D2 / 64, EDIM / 32, 2), dim3(32, 8)>>>(Wq, Wa);
    wsplit_big_kernel<<<dim3(D6 / 64, EDIM / 32), dim3(32, 8)>>>(Wc1);
    reduce_kernel<<<dim3(BATCH, 4), 256>>>((const float4*)Q, (const float4*)Vq,
                                           (const float4*)Aa, (const float4*)Va,
                                           qlen, alen);
    gemm_mma<0><<<dim3(EDIM / 32, BATCH / 64, 2), 128>>>(bq, ba);   // 640 CTAs
    gemm_mma<2><<<dim3(EDIM / 32, BATCH / 64), 128>>>(bc1, bc1);    // 320 CTAs
    bn_stats_kernel<<<BATCH / 64, 256>>>();
    gemv_kernel<<<BATCH / 8, 256>>>(gam, bet, Wc2, bc2, out);
}

// round 16
// speedup vs baseline: 1.0163x; 1.0010x over previous
#include <cuda_runtime.h>
#include <cuda_bf16.h>
#include <cstdint>
#include <math.h>

#define BATCH 1280
#define EDIM  512
#define D2    1024
#define D6    3072
#define TV    64
#define BN_EPS 1e-5f

#define ROWB 80              // padded smem row stride bytes (40 bf16)

// ---------------- device globals (scratch; zero-initialized) ----------------
__device__ __align__(16) float g_h [BATCH * EDIM];
__device__ __align__(16) __nv_bfloat16 g_qm_hi[BATCH * D2], g_qm_lo[BATCH * D2];
__device__ __align__(16) __nv_bfloat16 g_am_hi[BATCH * D2], g_am_lo[BATCH * D2];
__device__ __align__(16) __nv_bfloat16 g_X_hi[BATCH * D6],  g_X_lo[BATCH * D6];
__device__ __align__(16) __nv_bfloat16 g_WqT_hi[EDIM * D2],  g_WqT_lo[EDIM * D2];
__device__ __align__(16) __nv_bfloat16 g_WaT_hi[EDIM * D2],  g_WaT_lo[EDIM * D2];
__device__ __align__(16) __nv_bfloat16 g_Wc1T_hi[EDIM * D6], g_Wc1T_lo[EDIM * D6];
__device__ float g_sum[EDIM], g_sumsq[EDIM];

__device__ __forceinline__ void split_store(__nv_bfloat16* hi, __nv_bfloat16* lo,
                                            size_t idx, float v) {
    __nv_bfloat16 h = __float2bfloat16(v);
    hi[idx] = h;
    lo[idx] = __float2bfloat16(v - __bfloat162float(h));
}

__device__ __forceinline__ uint32_t pack_bf16x2(float a, float b) {
    __nv_bfloat16 ha = __float2bfloat16(a), hb = __float2bfloat16(b);
    uint16_t ua, ub;
    memcpy(&ua, &ha, 2); memcpy(&ub, &hb, 2);
    return (uint32_t)ua | ((uint32_t)ub << 16);
}

__device__ __forceinline__ uint32_t smem_u32(const void* p) {
    uint32_t a;
    asm("{ .reg .u64 t; cvta.to.shared.u64 t, %1; cvt.u32.u64 %0, t; }"
        : "=r"(a) : "l"(p));
    return a;
}

__device__ __forceinline__ void ldmat4(uint32_t* r, uint32_t addr) {
    asm volatile("ldmatrix.sync.aligned.m8n8.x4.shared.b16 {%0,%1,%2,%3}, [%4];"
                 : "=r"(r[0]), "=r"(r[1]), "=r"(r[2]), "=r"(r[3]) : "r"(addr));
}

__device__ __forceinline__ void mma_bf16(float* c, const uint32_t* a,
                                         uint32_t b0, uint32_t b1) {
    asm volatile(
        "mma.sync.aligned.m16n8k16.row.col.f32.bf16.bf16.f32 "
        "{%0,%1,%2,%3}, {%4,%5,%6,%7}, {%8,%9}, {%0,%1,%2,%3};"
        : "+f"(c[0]), "+f"(c[1]), "+f"(c[2]), "+f"(c[3])
        : "r"(a[0]), "r"(a[1]), "r"(a[2]), "r"(a[3]), "r"(b0), "r"(b1));
}

#define CP16(dst, src) \
    asm volatile("cp.async.cg.shared.global [%0], [%1], 16;" \
                 :: "r"(dst), "l"(src) : "memory")
#define CP_COMMIT() asm volatile("cp.async.commit_group;" ::: "memory")
#define CP_WAIT1()  asm volatile("cp.async.wait_group 1;" ::: "memory")

// ---------------- small weight transpose+split (Wq/Wa via z) + stats zero ---
__global__ void wsplit_small_kernel(const float* __restrict__ Wq,
                                    const float* __restrict__ Wa) {
    const int which = blockIdx.z;
    const float* W = which ? Wa : Wq;
    __nv_bfloat16* oh = which ? g_WaT_hi : g_WqT_hi;
    __nv_bfloat16* ol = which ? g_WaT_lo : g_WqT_lo;
    const int tid = threadIdx.y * 32 + threadIdx.x;
    if (which == 0 && blockIdx.x == 0 && blockIdx.y == 0) {
        g_sum[tid] = 0.f; g_sum[tid + 256] = 0.f;
        g_sumsq[tid] = 0.f; g_sumsq[tid + 256] = 0.f;
    }
    __shared__ float t[64][33];
    const int k0 = blockIdx.x * 64, n0 = blockIdx.y * 32;
    const int tx = threadIdx.x, ty = threadIdx.y;
    #pragma unroll
    for (int i = ty; i < 64; i += 8)
        t[i][tx] = W[(size_t)(k0 + i) * EDIM + n0 + tx];
    __syncthreads();
    #pragma unroll
    for (int i = ty; i < 32; i += 8) {
        const float v0 = t[2 * tx][i], v1 = t[2 * tx + 1][i];
        const __nv_bfloat16 h0 = __float2bfloat16(v0);
        const __nv_bfloat16 h1 = __float2bfloat16(v1);
        const size_t o = (size_t)(n0 + i) * D2 + k0 + 2 * tx;
        *(uint32_t*)&oh[o] = pack_bf16x2(v0, v1);
        *(uint32_t*)&ol[o] = pack_bf16x2(v0 - __bfloat162float(h0),
                                         v1 - __bfloat162float(h1));
    }
}

// ---------------- big weight transpose+split (Wc1) ---------------------------
__global__ void wsplit_big_kernel(const float* __restrict__ W) {
    __shared__ float t[64][33];
    const int k0 = blockIdx.x * 64, n0 = blockIdx.y * 32;
    const int tx = threadIdx.x, ty = threadIdx.y;
    #pragma unroll
    for (int i = ty; i < 64; i += 8)
        t[i][tx] = W[(size_t)(k0 + i) * EDIM + n0 + tx];
    __syncthreads();
    #pragma unroll
    for (int i = ty; i < 32; i += 8) {
        const float v0 = t[2 * tx][i], v1 = t[2 * tx + 1][i];
        const __nv_bfloat16 h0 = __float2bfloat16(v0);
        const __nv_bfloat16 h1 = __float2bfloat16(v1);
        const size_t o = (size_t)(n0 + i) * D6 + k0 + 2 * tx;
        *(uint32_t*)&g_Wc1T_hi[o] = pack_bf16x2(v0, v1);
        *(uint32_t*)&g_Wc1T_lo[o] = pack_bf16x2(v0 - __bfloat162float(h0),
                                                v1 - __bfloat162float(h1));
    }
}

// ---------------- fused sequence-mean reductions -> bf16 hi/lo directly -----
__global__ void reduce_kernel(const float4* __restrict__ Q,
                              const float4* __restrict__ Vq,
                              const float4* __restrict__ A,
                              const float4* __restrict__ Va,
                              const int* __restrict__ qlen,
                              const int* __restrict__ alen) {
    const int b = blockIdx.x;
    const int which = blockIdx.y;
    const int d4 = threadIdx.x;
    const int stride = BATCH * (D2 / 4);

    const float4* p;
    int L;
    if (which == 0)      { L = max(qlen[b], 1); p = Q  + b * (D2 / 4) + d4; }
    else if (which == 1) { L = TV;              p = Vq + b * (D2 / 4) + d4; }
    else if (which == 2) { L = max(alen[b], 1); p = A  + b * (D2 / 4) + d4; }
    else                 { L = TV;              p = Va + b * (D2 / 4) + d4; }

    float4 acc = make_float4(0.f, 0.f, 0.f, 0.f);
    #pragma unroll 8
    for (int t = 0; t < L; t++) {
        float4 v = p[t * stride];
        acc.x += v.x; acc.y += v.y; acc.z += v.z; acc.w += v.w;
    }
    const float inv = 1.f / (float)L;
    float vals[4] = {acc.x * inv, acc.y * inv, acc.z * inv, acc.w * inv};

    size_t base;
    __nv_bfloat16 *hi, *lo;
    if (which == 0)      { hi = g_qm_hi; lo = g_qm_lo; base = (size_t)b * D2 + 4 * d4; }
    else if (which == 1) { hi = g_X_hi;  lo = g_X_lo;  base = (size_t)b * D6 + EDIM + 4 * d4; }
    else if (which == 2) { hi = g_am_hi; lo = g_am_lo; base = (size_t)b * D2 + 4 * d4; }
    else                 { hi = g_X_hi;  lo = g_X_lo;  base = (size_t)b * D6 + 2048 + 4 * d4; }
    #pragma unroll
    for (int j = 0; j < 4; j++) split_store(hi, lo, base + j, vals[j]);
}

// ---------------- split-bf16 GEMM: cp.async 3-stage ring, 1 barrier/iter ----
// BM=64, BN=32, 4 warps (32x16 warp tiles). Fragment addressing as R11/R12.
// Slot written at iter it ((it+2)%3) was last READ at iter it-1; the top
// barrier of iter it orders all warps past that compute -> no trailing barrier.
// MODE 0: z=0: qm@WqT -> X[:,0:512); z=1: am@WaT -> X[:,1536:2048) (split-stored)
// MODE 2: X@Wc1T + bias + ELU -> g_h (fp32)
template <int MODE>
__global__ __launch_bounds__(128)
void gemm_mma(const float* __restrict__ bias0, const float* __restrict__ bias1) {
    constexpr int OA_L = 64 * ROWB;           // 5120
    constexpr int OB_H = 2 * 64 * ROWB;       // 10240
    constexpr int OB_L = OB_H + 32 * ROWB;    // 12800
    constexpr int SS   = OB_L + 32 * ROWB;    // 15360 per stage
    __shared__ __align__(16) unsigned char smem[3 * SS];   // 46080 < 48K

    const int tid = threadIdx.x;
    const int w = tid >> 5, l = tid & 31;
    const int wm = w & 1, wn = w >> 1;
    const int g = l >> 2, tg = l & 3;

    const __nv_bfloat16 *Ahi, *Alo, *Bhi, *Blo;
    const float* bias;
    int ldv, niter, colbase;
    if (MODE == 2) {
        Ahi = g_X_hi; Alo = g_X_lo; Bhi = g_Wc1T_hi; Blo = g_Wc1T_lo;
        bias = bias0; colbase = 0;
        ldv = D6 / 8; niter = D6 / 32;
    } else {
        if (blockIdx.z == 0) {
            Ahi = g_qm_hi; Alo = g_qm_lo; Bhi = g_WqT_hi; Blo = g_WqT_lo;
            bias = bias0; colbase = 0;
        } else {
            Ahi = g_am_hi; Alo = g_am_lo; Bhi = g_WaT_hi; Blo = g_WaT_lo;
            bias = bias1; colbase = 3 * EDIM;
        }
        ldv = D2 / 8; niter = D2 / 32;
    }

    const int bm = blockIdx.y * 64, bn = blockIdx.x * 32;
    const uint4* gAhi = (const uint4*)Ahi + (size_t)bm * ldv;
    const uint4* gAlo = (const uint4*)Alo + (size_t)bm * ldv;
    const uint4* gBhi = (const uint4*)Bhi + (size_t)bn * ldv;
    const uint4* gBlo = (const uint4*)Blo + (size_t)bn * ldv;

    const uint32_t S = smem_u32(smem);
    const int aRow = l & 15, aC = (l >> 4) * 16;
    const int bRow = ((l >> 4) & 1) * 8 + (l & 7), bC = ((l >> 3) & 1) * 16;
    const uint32_t aOffH = (wm * 32 + aRow) * ROWB + aC;
    const uint32_t aOffL = aOffH + OA_L;
    const uint32_t bOffH = OB_H + (wn * 16 + bRow) * ROWB + bC;
    const uint32_t bOffL = bOffH + (OB_L - OB_H);

    // copy mapping: A 64 rows x 4 segs (2 cp/thread per half); B 32 rows x 4
    const int cr0 = tid >> 2, cs0 = tid & 3;   // rows 0..31
    const int cr1 = cr0 + 32;                  // rows 32..63
    const uint32_t dA0 = cr0 * ROWB + cs0 * 16;
    const uint32_t dA1 = cr1 * ROWB + cs0 * 16;
    const uint32_t dB0 = OB_H + cr0 * ROWB + cs0 * 16;

    float c[2][2][4] = {};

    #define ISSUE_STAGE(slot, kv) do {                                        \
        const uint32_t D = S + (slot) * SS;                                   \
        CP16(D + dA0,          gAhi + cr0 * ldv + (kv) + cs0);                \
        CP16(D + dA1,          gAhi + cr1 * ldv + (kv) + cs0);                \
        CP16(D + dA0 + OA_L,   gAlo + cr0 * ldv + (kv) + cs0);                \
        CP16(D + dA1 + OA_L,   gAlo + cr1 * ldv + (kv) + cs0);                \
        CP16(D + dB0,          gBhi + cr0 * ldv + (kv) + cs0);                \
        CP16(D + dB0 + (OB_L - OB_H), gBlo + cr0 * ldv + (kv) + cs0);         \
        CP_COMMIT();                                                          \
    } while (0)

    ISSUE_STAGE(0, 0);
    ISSUE_STAGE(1, 4);

    int slot = 0, nslot = 2;
    for (int it = 0; it < niter; it++) {
        CP_WAIT1();                 // stage[slot] landed (newest may be in flight)
        __syncthreads();            // also orders prior iter's reads of nslot

        if (it + 2 < niter) {
            ISSUE_STAGE(nslot, (it + 2) * 4);
            nslot = (nslot == 2) ? 0 : nslot + 1;
        }

        const uint32_t B = S + slot * SS;
        slot = (slot == 2) ? 0 : slot + 1;
        #pragma unroll
        for (int ks = 0; ks < 2; ks++) {
            const int kb = ks * 32;
            uint32_t ah[2][4], al[2][4], bh[4], bl[4];
            #pragma unroll
            for (int mt = 0; mt < 2; mt++) {
                ldmat4(ah[mt], B + aOffH + mt * (16 * ROWB) + kb);
                ldmat4(al[mt], B + aOffL + mt * (16 * ROWB) + kb);
            }
            ldmat4(bh, B + bOffH + kb);
            ldmat4(bl, B + bOffL + kb);
            #pragma unroll
            for (int mt = 0; mt < 2; mt++)
                #pragma unroll
                for (int h = 0; h < 2; h++) {
                    float* acc = c[mt][h];
                    mma_bf16(acc, ah[mt], bh[h * 2], bh[h * 2 + 1]);
                    mma_bf16(acc, al[mt], bh[h * 2], bh[h * 2 + 1]);
                    mma_bf16(acc, ah[mt], bl[h * 2], bl[h * 2 + 1]);
                }
        }
        // no trailing barrier: next iter's top barrier provides the ordering
    }
    #undef ISSUE_STAGE

    #pragma unroll
    for (int mt = 0; mt < 2; mt++) {
        #pragma unroll
        for (int h = 0; h < 2; h++) {
            const int col = bn + wn * 16 + h * 8 + tg * 2;
            const float b0v = bias[col], b1v = bias[col + 1];
            const int r0 = bm + wm * 32 + mt * 16 + g;
            float v00 = c[mt][h][0] + b0v;
            float v01 = c[mt][h][1] + b1v;
            float v10 = c[mt][h][2] + b0v;
            float v11 = c[mt][h][3] + b1v;
            if (MODE == 2) {
                if (v00 <= 0.f) v00 = expm1f(v00);
                if (v01 <= 0.f) v01 = expm1f(v01);
                if (v10 <= 0.f) v10 = expm1f(v10);
                if (v11 <= 0.f) v11 = expm1f(v11);
                g_h[(size_t)r0 * EDIM + col]           = v00;
                g_h[(size_t)r0 * EDIM + col + 1]       = v01;
                g_h[(size_t)(r0 + 8) * EDIM + col]     = v10;
                g_h[(size_t)(r0 + 8) * EDIM + col + 1] = v11;
            } else {
                const size_t base0 = (size_t)r0 * D6 + colbase + col;
                const size_t base1 = (size_t)(r0 + 8) * D6 + colbase + col;
                split_store(g_X_hi, g_X_lo, base0, v00);
                split_store(g_X_hi, g_X_lo, base0 + 1, v01);
                split_store(g_X_hi, g_X_lo, base1, v10);
                split_store(g_X_hi, g_X_lo, base1 + 1, v11);
            }
        }
    }
}

// ---------------- BN batch stats --------------------------------------------
__global__ void bn_stats_kernel() {
    const int r0 = blockIdx.x * 64;
    for (int c = threadIdx.x; c < EDIM; c += blockDim.x) {
        float s = 0.f, s2 = 0.f;
        #pragma unroll 8
        for (int r = 0; r < 64; r++) {
            float v = g_h[(size_t)(r0 + r) * EDIM + c];
            s += v; s2 += v * v;
        }
        atomicAdd(&g_sum[c], s);
        atomicAdd(&g_sumsq[c], s2);
    }
}

// ---------------- fused BN-finalize + GEMV ----------------------------------
__global__ __launch_bounds__(256) void gemv_kernel(const float* __restrict__ gamma,
                                                   const float* __restrict__ beta,
                                                   const float* __restrict__ Wc2,
                                                   const float* __restrict__ bc2,
                                                   float* __restrict__ out) {
    __shared__ float wc[EDIM];
    __shared__ float red[256];
    __shared__ float cst_s;
    const int t = threadIdx.x;
    const float invB = 1.f / (float)BATCH;
    float part = 0.f;
    #pragma unroll
    for (int i = 0; i < 2; i++) {
        const int c = t + i * 256;
        const float mu  = g_sum[c] * invB;
        const float var = fmaxf(g_sumsq[c] * invB - mu * mu, 0.f);
        const float sc  = gamma[c] * rsqrtf(var + BN_EPS);
        const float w2  = Wc2[c];
        wc[c] = sc * w2;
        part += (beta[c] - mu * sc) * w2;
    }
    red[t] = part;
    __syncthreads();
    for (int off = 128; off > 0; off >>= 1) {
        if (t < off) red[t] += red[t + off];
        __syncthreads();
    }
    if (t == 0) cst_s = red[0] + bc2[0];
    __syncthreads();

    const int warp = t >> 5, lane = t & 31;
    const int b = blockIdx.x * 8 + warp;
    const float* hr = g_h + (size_t)b * EDIM;
    float s = 0.f;
    #pragma unroll
    for (int c = lane; c < EDIM; c += 32) s += hr[c] * wc[c];
    #pragma unroll
    for (int off = 16; off > 0; off >>= 1) s += __shfl_down_sync(0xffffffffu, s, off);
    if (lane == 0) out[b] = s + cst_s;
}

// ---------------- launcher --------------------------------------------------
extern "C" void kernel_launch(void* const* d_in, const int* in_sizes, int n_in,
                              void* d_out, int out_size) {
    const float* Q    = (const float*)d_in[0];
    const float* Vq   = (const float*)d_in[1];
    const float* Aa   = (const float*)d_in[2];
    const float* Va   = (const float*)d_in[3];
    const int*   qlen = (const int*)d_in[4];
    const int*   alen = (const int*)d_in[5];
    const float* Wq   = (const float*)d_in[6];
    const float* bq   = (const float*)d_in[7];
    const float* Wa   = (const float*)d_in[8];
    const float* ba   = (const float*)d_in[9];
    const float* Wc1  = (const float*)d_in[10];
    const float* bc1  = (const float*)d_in[11];
    const float* gam  = (const float*)d_in[12];
    const float* bet  = (const float*)d_in[13];
    const float* Wc2  = (const float*)d_in[14];
    const float* bc2  = (const float*)d_in[15];
    float* out = (float*)d_out;

    // raise the smem carveout so 46KB/CTA admits ~4 CTAs/SM (one-time, cached
    // by the driver; legal under graph capture — no alloc, no sync)
    static bool configured = false;
    if (!configured) {
        cudaFuncSetAttribute(gemm_mma<0>,
                             cudaFuncAttributePreferredSharedMemoryCarveout, 100);
        cudaFuncSetAttribute(gemm_mma<2>,
                             cudaFuncAttributePreferredSharedMemoryCarveout, 100);
        configured = true;
    }

    wsplit_small_kernel<<<dim3(D2 / 64, EDIM / 32, 2), dim3(32, 8)>>>(Wq, Wa);
    wsplit_big_kernel<<<dim3(D6 / 64, EDIM / 32), dim3(32, 8)>>>(Wc1);
    reduce_kernel<<<dim3(BATCH, 4), 256>>>((const float4*)Q, (const float4*)Vq,
                                           (const float4*)Aa, (const float4*)Va,
                                           qlen, alen);
    gemm_mma<0><<<dim3(EDIM / 32, BATCH / 64, 2), 128>>>(bq, ba);   // 640 CTAs
    gemm_mma<2><<<dim3(EDIM / 32, BATCH / 64), 128>>>(bc1, bc1);    // 320 CTAs
    bn_stats_kernel<<<BATCH / 64, 256>>>();
    gemv_kernel<<<BATCH / 8, 256>>>(gam, bet, Wc2, bc2, out);
}

// round 17
// speedup vs baseline: 1.0619x; 1.0449x over previous
#include <cuda_runtime.h>
#include <cuda_bf16.h>
#include <cstdint>
#include <math.h>

#define BATCH 1280
#define EDIM  512
#define D2    1024
#define D6    3072
#define TV    64
#define BN_EPS 1e-5f

#define ROWB 80              // padded smem row stride bytes (40 bf16)

// ---------------- device globals (scratch; zero-initialized) ----------------
__device__ __align__(16) float g_h [BATCH * EDIM];
__device__ __align__(16) __nv_bfloat16 g_qm_hi[BATCH * D2], g_qm_lo[BATCH * D2];
__device__ __align__(16) __nv_bfloat16 g_am_hi[BATCH * D2], g_am_lo[BATCH * D2];
__device__ __align__(16) __nv_bfloat16 g_X_hi[BATCH * D6],  g_X_lo[BATCH * D6];
__device__ __align__(16) __nv_bfloat16 g_WqT_hi[EDIM * D2],  g_WqT_lo[EDIM * D2];
__device__ __align__(16) __nv_bfloat16 g_WaT_hi[EDIM * D2],  g_WaT_lo[EDIM * D2];
__device__ __align__(16) __nv_bfloat16 g_Wc1T_hi[EDIM * D6], g_Wc1T_lo[EDIM * D6];
__device__ float g_sum[EDIM], g_sumsq[EDIM];

__device__ __forceinline__ void split_store(__nv_bfloat16* hi, __nv_bfloat16* lo,
                                            size_t idx, float v) {
    __nv_bfloat16 h = __float2bfloat16(v);
    hi[idx] = h;
    lo[idx] = __float2bfloat16(v - __bfloat162float(h));
}

__device__ __forceinline__ uint32_t pack_bf16x2(float a, float b) {
    __nv_bfloat16 ha = __float2bfloat16(a), hb = __float2bfloat16(b);
    uint16_t ua, ub;
    memcpy(&ua, &ha, 2); memcpy(&ub, &hb, 2);
    return (uint32_t)ua | ((uint32_t)ub << 16);
}

__device__ __forceinline__ uint32_t smem_u32(const void* p) {
    uint32_t a;
    asm("{ .reg .u64 t; cvta.to.shared.u64 t, %1; cvt.u32.u64 %0, t; }"
        : "=r"(a) : "l"(p));
    return a;
}

__device__ __forceinline__ void ldmat4(uint32_t* r, uint32_t addr) {
    asm volatile("ldmatrix.sync.aligned.m8n8.x4.shared.b16 {%0,%1,%2,%3}, [%4];"
                 : "=r"(r[0]), "=r"(r[1]), "=r"(r[2]), "=r"(r[3]) : "r"(addr));
}

__device__ __forceinline__ void mma_bf16(float* c, const uint32_t* a,
                                         uint32_t b0, uint32_t b1) {
    asm volatile(
        "mma.sync.aligned.m16n8k16.row.col.f32.bf16.bf16.f32 "
        "{%0,%1,%2,%3}, {%4,%5,%6,%7}, {%8,%9}, {%0,%1,%2,%3};"
        : "+f"(c[0]), "+f"(c[1]), "+f"(c[2]), "+f"(c[3])
        : "r"(a[0]), "r"(a[1]), "r"(a[2]), "r"(a[3]), "r"(b0), "r"(b1));
}

#define CP16(dst, src) \
    asm volatile("cp.async.cg.shared.global [%0], [%1], 16;" \
                 :: "r"(dst), "l"(src) : "memory")
#define CP_COMMIT() asm volatile("cp.async.commit_group;" ::: "memory")
#define CP_WAIT1()  asm volatile("cp.async.wait_group 1;" ::: "memory")

// ---------------- small weight transpose+split (Wq/Wa via z) + stats zero ---
__global__ void wsplit_small_kernel(const float* __restrict__ Wq,
                                    const float* __restrict__ Wa) {
    const int which = blockIdx.z;
    const float* W = which ? Wa : Wq;
    __nv_bfloat16* oh = which ? g_WaT_hi : g_WqT_hi;
    __nv_bfloat16* ol = which ? g_WaT_lo : g_WqT_lo;
    const int tid = threadIdx.y * 32 + threadIdx.x;
    if (which == 0 && blockIdx.x == 0 && blockIdx.y == 0) {
        g_sum[tid] = 0.f; g_sum[tid + 256] = 0.f;
        g_sumsq[tid] = 0.f; g_sumsq[tid + 256] = 0.f;
    }
    __shared__ float t[64][33];
    const int k0 = blockIdx.x * 64, n0 = blockIdx.y * 32;
    const int tx = threadIdx.x, ty = threadIdx.y;
    #pragma unroll
    for (int i = ty; i < 64; i += 8)
        t[i][tx] = W[(size_t)(k0 + i) * EDIM + n0 + tx];
    __syncthreads();
    #pragma unroll
    for (int i = ty; i < 32; i += 8) {
        const float v0 = t[2 * tx][i], v1 = t[2 * tx + 1][i];
        const __nv_bfloat16 h0 = __float2bfloat16(v0);
        const __nv_bfloat16 h1 = __float2bfloat16(v1);
        const size_t o = (size_t)(n0 + i) * D2 + k0 + 2 * tx;
        *(uint32_t*)&oh[o] = pack_bf16x2(v0, v1);
        *(uint32_t*)&ol[o] = pack_bf16x2(v0 - __bfloat162float(h0),
                                         v1 - __bfloat162float(h1));
    }
}

// ---------------- big weight transpose+split (Wc1) ---------------------------
__global__ void wsplit_big_kernel(const float* __restrict__ W) {
    __shared__ float t[64][33];
    const int k0 = blockIdx.x * 64, n0 = blockIdx.y * 32;
    const int tx = threadIdx.x, ty = threadIdx.y;
    #pragma unroll
    for (int i = ty; i < 64; i += 8)
        t[i][tx] = W[(size_t)(k0 + i) * EDIM + n0 + tx];
    __syncthreads();
    #pragma unroll
    for (int i = ty; i < 32; i += 8) {
        const float v0 = t[2 * tx][i], v1 = t[2 * tx + 1][i];
        const __nv_bfloat16 h0 = __float2bfloat16(v0);
        const __nv_bfloat16 h1 = __float2bfloat16(v1);
        const size_t o = (size_t)(n0 + i) * D6 + k0 + 2 * tx;
        *(uint32_t*)&g_Wc1T_hi[o] = pack_bf16x2(v0, v1);
        *(uint32_t*)&g_Wc1T_lo[o] = pack_bf16x2(v0 - __bfloat162float(h0),
                                                v1 - __bfloat162float(h1));
    }
}

// ---------------- fused sequence-mean reductions -> bf16 hi/lo directly -----
// pair=0: which = {0:qm, 2:am} (masked means feeding gemm<0>)
// pair=1: which = {1:Vq, 3:Va} (visual means -> X cols, disjoint from gemm<0>)
__global__ void reduce_kernel(const float4* __restrict__ Q,
                              const float4* __restrict__ Vq,
                              const float4* __restrict__ A,
                              const float4* __restrict__ Va,
                              const int* __restrict__ qlen,
                              const int* __restrict__ alen,
                              int pair) {
    const int b = blockIdx.x;
    const int which = blockIdx.y * 2 + pair;
    const int d4 = threadIdx.x;
    const int stride = BATCH * (D2 / 4);

    const float4* p;
    int L;
    if (which == 0)      { L = max(qlen[b], 1); p = Q  + b * (D2 / 4) + d4; }
    else if (which == 1) { L = TV;              p = Vq + b * (D2 / 4) + d4; }
    else if (which == 2) { L = max(alen[b], 1); p = A  + b * (D2 / 4) + d4; }
    else                 { L = TV;              p = Va + b * (D2 / 4) + d4; }

    float4 acc = make_float4(0.f, 0.f, 0.f, 0.f);
    #pragma unroll 8
    for (int t = 0; t < L; t++) {
        float4 v = p[t * stride];
        acc.x += v.x; acc.y += v.y; acc.z += v.z; acc.w += v.w;
    }
    const float inv = 1.f / (float)L;
    float vals[4] = {acc.x * inv, acc.y * inv, acc.z * inv, acc.w * inv};

    size_t base;
    __nv_bfloat16 *hi, *lo;
    if (which == 0)      { hi = g_qm_hi; lo = g_qm_lo; base = (size_t)b * D2 + 4 * d4; }
    else if (which == 1) { hi = g_X_hi;  lo = g_X_lo;  base = (size_t)b * D6 + EDIM + 4 * d4; }
    else if (which == 2) { hi = g_am_hi; lo = g_am_lo; base = (size_t)b * D2 + 4 * d4; }
    else                 { hi = g_X_hi;  lo = g_X_lo;  base = (size_t)b * D6 + 2048 + 4 * d4; }
    #pragma unroll
    for (int j = 0; j < 4; j++) split_store(hi, lo, base + j, vals[j]);
}

// ---------------- split-bf16 GEMM: cp.async 3-stage ring, 1 barrier/iter ----
// BM=64, BN=32, 4 warps (32x16 warp tiles). Fragment addressing as R11/R12.
// MODE 0: z=0: qm@WqT -> X[:,0:512); z=1: am@WaT -> X[:,1536:2048) (split-stored)
// MODE 2: X@Wc1T + bias + ELU -> g_h (fp32)
template <int MODE>
__global__ __launch_bounds__(128)
void gemm_mma(const float* __restrict__ bias0, const float* __restrict__ bias1) {
    constexpr int OA_L = 64 * ROWB;           // 5120
    constexpr int OB_H = 2 * 64 * ROWB;       // 10240
    constexpr int OB_L = OB_H + 32 * ROWB;    // 12800
    constexpr int SS   = OB_L + 32 * ROWB;    // 15360 per stage
    __shared__ __align__(16) unsigned char smem[3 * SS];   // 46080 < 48K

    const int tid = threadIdx.x;
    const int w = tid >> 5, l = tid & 31;
    const int wm = w & 1, wn = w >> 1;
    const int g = l >> 2, tg = l & 3;

    const __nv_bfloat16 *Ahi, *Alo, *Bhi, *Blo;
    const float* bias;
    int ldv, niter, colbase;
    if (MODE == 2) {
        Ahi = g_X_hi; Alo = g_X_lo; Bhi = g_Wc1T_hi; Blo = g_Wc1T_lo;
        bias = bias0; colbase = 0;
        ldv = D6 / 8; niter = D6 / 32;
    } else {
        if (blockIdx.z == 0) {
            Ahi = g_qm_hi; Alo = g_qm_lo; Bhi = g_WqT_hi; Blo = g_WqT_lo;
            bias = bias0; colbase = 0;
        } else {
            Ahi = g_am_hi; Alo = g_am_lo; Bhi = g_WaT_hi; Blo = g_WaT_lo;
            bias = bias1; colbase = 3 * EDIM;
        }
        ldv = D2 / 8; niter = D2 / 32;
    }

    const int bm = blockIdx.y * 64, bn = blockIdx.x * 32;
    const uint4* gAhi = (const uint4*)Ahi + (size_t)bm * ldv;
    const uint4* gAlo = (const uint4*)Alo + (size_t)bm * ldv;
    const uint4* gBhi = (const uint4*)Bhi + (size_t)bn * ldv;
    const uint4* gBlo = (const uint4*)Blo + (size_t)bn * ldv;

    const uint32_t S = smem_u32(smem);
    const int aRow = l & 15, aC = (l >> 4) * 16;
    const int bRow = ((l >> 4) & 1) * 8 + (l & 7), bC = ((l >> 3) & 1) * 16;
    const uint32_t aOffH = (wm * 32 + aRow) * ROWB + aC;
    const uint32_t aOffL = aOffH + OA_L;
    const uint32_t bOffH = OB_H + (wn * 16 + bRow) * ROWB + bC;
    const uint32_t bOffL = bOffH + (OB_L - OB_H);

    const int cr0 = tid >> 2, cs0 = tid & 3;   // rows 0..31
    const int cr1 = cr0 + 32;                  // rows 32..63
    const uint32_t dA0 = cr0 * ROWB + cs0 * 16;
    const uint32_t dA1 = cr1 * ROWB + cs0 * 16;
    const uint32_t dB0 = OB_H + cr0 * ROWB + cs0 * 16;

    float c[2][2][4] = {};

    #define ISSUE_STAGE(slot, kv) do {                                        \
        const uint32_t D = S + (slot) * SS;                                   \
        CP16(D + dA0,          gAhi + cr0 * ldv + (kv) + cs0);                \
        CP16(D + dA1,          gAhi + cr1 * ldv + (kv) + cs0);                \
        CP16(D + dA0 + OA_L,   gAlo + cr0 * ldv + (kv) + cs0);                \
        CP16(D + dA1 + OA_L,   gAlo + cr1 * ldv + (kv) + cs0);                \
        CP16(D + dB0,          gBhi + cr0 * ldv + (kv) + cs0);                \
        CP16(D + dB0 + (OB_L - OB_H), gBlo + cr0 * ldv + (kv) + cs0);         \
        CP_COMMIT();                                                          \
    } while (0)

    ISSUE_STAGE(0, 0);
    ISSUE_STAGE(1, 4);

    int slot = 0, nslot = 2;
    for (int it = 0; it < niter; it++) {
        CP_WAIT1();
        __syncthreads();

        if (it + 2 < niter) {
            ISSUE_STAGE(nslot, (it + 2) * 4);
            nslot = (nslot == 2) ? 0 : nslot + 1;
        }

        const uint32_t B = S + slot * SS;
        slot = (slot == 2) ? 0 : slot + 1;
        #pragma unroll
        for (int ks = 0; ks < 2; ks++) {
            const int kb = ks * 32;
            uint32_t ah[2][4], al[2][4], bh[4], bl[4];
            #pragma unroll
            for (int mt = 0; mt < 2; mt++) {
                ldmat4(ah[mt], B + aOffH + mt * (16 * ROWB) + kb);
                ldmat4(al[mt], B + aOffL + mt * (16 * ROWB) + kb);
            }
            ldmat4(bh, B + bOffH + kb);
            ldmat4(bl, B + bOffL + kb);
            #pragma unroll
            for (int mt = 0; mt < 2; mt++)
                #pragma unroll
                for (int h = 0; h < 2; h++) {
                    float* acc = c[mt][h];
                    mma_bf16(acc, ah[mt], bh[h * 2], bh[h * 2 + 1]);
                    mma_bf16(acc, al[mt], bh[h * 2], bh[h * 2 + 1]);
                    mma_bf16(acc, ah[mt], bl[h * 2], bl[h * 2 + 1]);
                }
        }
    }
    #undef ISSUE_STAGE

    #pragma unroll
    for (int mt = 0; mt < 2; mt++) {
        #pragma unroll
        for (int h = 0; h < 2; h++) {
            const int col = bn + wn * 16 + h * 8 + tg * 2;
            const float b0v = bias[col], b1v = bias[col + 1];
            const int r0 = bm + wm * 32 + mt * 16 + g;
            float v00 = c[mt][h][0] + b0v;
            float v01 = c[mt][h][1] + b1v;
            float v10 = c[mt][h][2] + b0v;
            float v11 = c[mt][h][3] + b1v;
            if (MODE == 2) {
                if (v00 <= 0.f) v00 = expm1f(v00);
                if (v01 <= 0.f) v01 = expm1f(v01);
                if (v10 <= 0.f) v10 = expm1f(v10);
                if (v11 <= 0.f) v11 = expm1f(v11);
                g_h[(size_t)r0 * EDIM + col]           = v00;
                g_h[(size_t)r0 * EDIM + col + 1]       = v01;
                g_h[(size_t)(r0 + 8) * EDIM + col]     = v10;
                g_h[(size_t)(r0 + 8) * EDIM + col + 1] = v11;
            } else {
                const size_t base0 = (size_t)r0 * D6 + colbase + col;
                const size_t base1 = (size_t)(r0 + 8) * D6 + colbase + col;
                split_store(g_X_hi, g_X_lo, base0, v00);
                split_store(g_X_hi, g_X_lo, base0 + 1, v01);
                split_store(g_X_hi, g_X_lo, base1, v10);
                split_store(g_X_hi, g_X_lo, base1 + 1, v11);
            }
        }
    }
}

// ---------------- BN batch stats --------------------------------------------
__global__ void bn_stats_kernel() {
    const int r0 = blockIdx.x * 64;
    for (int c = threadIdx.x; c < EDIM; c += blockDim.x) {
        float s = 0.f, s2 = 0.f;
        #pragma unroll 8
        for (int r = 0; r < 64; r++) {
            float v = g_h[(size_t)(r0 + r) * EDIM + c];
            s += v; s2 += v * v;
        }
        atomicAdd(&g_sum[c], s);
        atomicAdd(&g_sumsq[c], s2);
    }
}

// ---------------- fused BN-finalize + GEMV ----------------------------------
__global__ __launch_bounds__(256) void gemv_kernel(const float* __restrict__ gamma,
                                                   const float* __restrict__ beta,
                                                   const float* __restrict__ Wc2,
                                                   const float* __restrict__ bc2,
                                                   float* __restrict__ out) {
    __shared__ float wc[EDIM];
    __shared__ float red[256];
    __shared__ float cst_s;
    const int t = threadIdx.x;
    const float invB = 1.f / (float)BATCH;
    float part = 0.f;
    #pragma unroll
    for (int i = 0; i < 2; i++) {
        const int c = t + i * 256;
        const float mu  = g_sum[c] * invB;
        const float var = fmaxf(g_sumsq[c] * invB - mu * mu, 0.f);
        const float sc  = gamma[c] * rsqrtf(var + BN_EPS);
        const float w2  = Wc2[c];
        wc[c] = sc * w2;
        part += (beta[c] - mu * sc) * w2;
    }
    red[t] = part;
    __syncthreads();
    for (int off = 128; off > 0; off >>= 1) {
        if (t < off) red[t] += red[t + off];
        __syncthreads();
    }
    if (t == 0) cst_s = red[0] + bc2[0];
    __syncthreads();

    const int warp = t >> 5, lane = t & 31;
    const int b = blockIdx.x * 8 + warp;
    const float* hr = g_h + (size_t)b * EDIM;
    float s = 0.f;
    #pragma unroll
    for (int c = lane; c < EDIM; c += 32) s += hr[c] * wc[c];
    #pragma unroll
    for (int off = 16; off > 0; off >>= 1) s += __shfl_down_sync(0xffffffffu, s, off);
    if (lane == 0) out[b] = s + cst_s;
}

// ---------------- launcher --------------------------------------------------
extern "C" void kernel_launch(void* const* d_in, const int* in_sizes, int n_in,
                              void* d_out, int out_size) {
    const float* Q    = (const float*)d_in[0];
    const float* Vq   = (const float*)d_in[1];
    const float* Aa   = (const float*)d_in[2];
    const float* Va   = (const float*)d_in[3];
    const int*   qlen = (const int*)d_in[4];
    const int*   alen = (const int*)d_in[5];
    const float* Wq   = (const float*)d_in[6];
    const float* bq   = (const float*)d_in[7];
    const float* Wa   = (const float*)d_in[8];
    const float* ba   = (const float*)d_in[9];
    const float* Wc1  = (const float*)d_in[10];
    const float* bc1  = (const float*)d_in[11];
    const float* gam  = (const float*)d_in[12];
    const float* bet  = (const float*)d_in[13];
    const float* Wc2  = (const float*)d_in[14];
    const float* bc2  = (const float*)d_in[15];
    float* out = (float*)d_out;

    // one-time setup on the (uncaptured) correctness call; replayed calls see
    // identical launch/event structure. No device memory is allocated.
    static cudaStream_t s2 = nullptr;
    static cudaEvent_t eFork, eQA, eG0;
    if (s2 == nullptr) {
        cudaStreamCreateWithFlags(&s2, cudaStreamNonBlocking);
        cudaEventCreateWithFlags(&eFork, cudaEventDisableTiming);
        cudaEventCreateWithFlags(&eQA,   cudaEventDisableTiming);
        cudaEventCreateWithFlags(&eG0,   cudaEventDisableTiming);
        cudaFuncSetAttribute(gemm_mma<0>,
                             cudaFuncAttributePreferredSharedMemoryCarveout, 100);
        cudaFuncSetAttribute(gemm_mma<2>,
                             cudaFuncAttributePreferredSharedMemoryCarveout, 100);
    }

    // fork s2 off the capture stream
    cudaEventRecord(eFork, 0);
    cudaStreamWaitEvent(s2, eFork, 0);

    // s2: weight prep (independent of inputs' reductions)
    wsplit_small_kernel<<<dim3(D2 / 64, EDIM / 32, 2), dim3(32, 8), 0, s2>>>(Wq, Wa);
    wsplit_big_kernel<<<dim3(D6 / 64, EDIM / 32), dim3(32, 8), 0, s2>>>(Wc1);

    // stream0: masked means (qm, am) — the only reduce gemm<0> needs
    reduce_kernel<<<dim3(BATCH, 2), 256>>>((const float4*)Q, (const float4*)Vq,
                                           (const float4*)Aa, (const float4*)Va,
                                           qlen, alen, 0);
    cudaEventRecord(eQA, 0);

    // s2: small GEMMs once qa + weights ready — overlaps with reduce_v below
    cudaStreamWaitEvent(s2, eQA, 0);
    gemm_mma<0><<<dim3(EDIM / 32, BATCH / 64, 2), 128, 0, s2>>>(bq, ba);
    cudaEventRecord(eG0, s2);

    // stream0: visual means (X cols disjoint from gemm<0>'s) — bulk of DRAM
    reduce_kernel<<<dim3(BATCH, 2), 256>>>((const float4*)Q, (const float4*)Vq,
                                           (const float4*)Aa, (const float4*)Va,
                                           qlen, alen, 1);

    // join: big GEMM needs full X
    cudaStreamWaitEvent(0, eG0, 0);
    gemm_mma<2><<<dim3(EDIM / 32, BATCH / 64), 128>>>(bc1, bc1);
    bn_stats_kernel<<<BATCH / 64, 256>>>();
    gemv_kernel<<<BATCH / 8, 256>>>(gam, bet, Wc2, bc2, out);
}